// round 6
// baseline (speedup 1.0000x reference)
#include <cuda_runtime.h>
#include <cuda_fp16.h>
#include <cstdint>

#define BB 2
#define SS 2048
#define DD 1024
#define HH 16
#define DK 64
#define MROWS (BB*SS)
#define NEGV -1000000000.0f

// ---------------- scratch ----------------
__device__ __align__(128) __half g_a16[(size_t)MROWS*DD];
__device__ __align__(128) __half g_w16[(size_t)DD*DD];
__device__ __align__(128) __half g_qh16[(size_t)BB*HH*SS*DK];  // (z,s,dk)
__device__ __align__(128) __half g_kh16[(size_t)BB*HH*SS*DK];  // (z,s,dk)
__device__ __align__(128) __half g_vt16[(size_t)BB*HH*DK*SS];  // (z,dk,s)
__device__ __align__(128) __half g_p16[(size_t)BB*HH*SS*SS];   // fp16 p_attn
__device__ float g_pattn_scratch[(size_t)BB*HH*SS*SS];         // fallback

// ---------------- helpers ----------------
__device__ __forceinline__ uint32_t smem_u32(const void* p) {
    uint32_t a;
    asm("{ .reg .u64 t; cvta.to.shared.u64 t, %1; cvt.u32.u64 %0, t; }" : "=r"(a) : "l"(p));
    return a;
}

#define CP_ASYNC16(dst, src) \
    asm volatile("cp.async.cg.shared.global [%0], [%1], 16;" :: "r"(dst), "l"(src) : "memory")
#define CP_COMMIT() asm volatile("cp.async.commit_group;" ::: "memory")
#define CP_WAIT(n)  asm volatile("cp.async.wait_group %0;" :: "n"(n) : "memory")

__device__ __forceinline__ void ldm_x4(uint32_t addr, uint32_t& r0, uint32_t& r1,
                                       uint32_t& r2, uint32_t& r3) {
    asm volatile("ldmatrix.sync.aligned.m8n8.x4.shared.b16 {%0,%1,%2,%3}, [%4];"
                 : "=r"(r0), "=r"(r1), "=r"(r2), "=r"(r3) : "r"(addr));
}

__device__ __forceinline__ void mma16816(float* c, const uint32_t* a, const uint32_t* b) {
    asm volatile("mma.sync.aligned.m16n8k16.row.col.f32.f16.f16.f32 "
                 "{%0,%1,%2,%3},{%4,%5,%6,%7},{%8,%9},{%0,%1,%2,%3};"
                 : "+f"(c[0]), "+f"(c[1]), "+f"(c[2]), "+f"(c[3])
                 : "r"(a[0]), "r"(a[1]), "r"(a[2]), "r"(a[3]), "r"(b[0]), "r"(b[1]));
}

// (rows x 32 half) tile, 80B padded rows
__device__ __forceinline__ void ld_tile(uint32_t dst, const __half* g, int ldh,
                                        int rows, int tid) {
    for (int ci = tid; ci < rows * 4; ci += 256) {
        int r = ci >> 2, c = ci & 3;
        CP_ASYNC16(dst + (uint32_t)(r * 80 + c * 16), g + (size_t)r * ldh + c * 8);
    }
}

// (128 x 64 half) tile as 2 chunks of (128 x 32), chunk stride 10240B
__device__ __forceinline__ void ld_tile64(uint32_t dst, const __half* g, int tid) {
#pragma unroll
    for (int i = 0; i < 4; i++) {
        int ci = tid + i * 256;
        int r = ci >> 3, c = ci & 7;
        int ch = c >> 2, cc = c & 3;
        CP_ASYNC16(dst + (uint32_t)(ch * 10240 + r * 80 + cc * 16),
                   g + (size_t)r * DK + c * 8);
    }
}

// ============================================================================
// Unified fp16 MMA GEMM (projections / AV)
// ============================================================================
template<int WG_N, int WMI, int MODE>
__global__ __launch_bounds__(256) void tc_mm(
    const __half* __restrict__ A, int lda, size_t aZ,
    const __half* __restrict__ B, int ldb, size_t bZ,
    int K,
    const float* __restrict__ bias,
    float* __restrict__ outF,
    __half* __restrict__ outH)
{
    constexpr int BN  = WG_N * 32;
    constexpr int BM  = (8 / WG_N) * WMI * 16;
    constexpr int ASZ = BM * 80;
    constexpr int BSZ = BN * 80;
    constexpr int STG = ASZ + BSZ;
    constexpr int S   = 4;

    extern __shared__ char smraw[];
    char* sm = (char*)(((uintptr_t)smraw + 127) & ~(uintptr_t)127);
    uint32_t smu = smem_u32(sm);

    const int tid  = threadIdx.x;
    const int w    = tid >> 5, lane = tid & 31;
    const int bn   = blockIdx.x * BN, bm = blockIdx.y * BM;
    const int z    = blockIdx.z;

    A += (size_t)z * aZ + (size_t)bm * lda;
    B += (size_t)z * bZ + (size_t)bn * ldb;

    const int wm = (w / WG_N) * (WMI * 16);
    const int wn = (w % WG_N) * 32;

    float acc[WMI][4][4];
#pragma unroll
    for (int mi = 0; mi < WMI; mi++)
#pragma unroll
        for (int nt = 0; nt < 4; nt++)
#pragma unroll
            for (int x = 0; x < 4; x++) acc[mi][nt][x] = 0.f;

    const int NK = K / 32;
#pragma unroll
    for (int s = 0; s < S - 1; s++) {
        if (s < NK) {
            ld_tile(smu + s * STG,       A + s * 32, lda, BM, tid);
            ld_tile(smu + s * STG + ASZ, B + s * 32, ldb, BN, tid);
        }
        CP_COMMIT();
    }

    const int rA = (lane & 7) + ((lane >> 3) & 1) * 8;
    const int kO = ((lane >> 4) << 3) * 2;

    for (int kt = 0; kt < NK; kt++) {
        CP_WAIT(S - 2);
        __syncthreads();
        uint32_t sA = smu + (kt % S) * STG;
        uint32_t sB = sA + ASZ;
#pragma unroll
        for (int ks = 0; ks < 2; ks++) {
            uint32_t a[WMI][4], bf[4][2];
            uint32_t kb = (uint32_t)(ks * 32 + kO);
#pragma unroll
            for (int mi = 0; mi < WMI; mi++)
                ldm_x4(sA + (uint32_t)((wm + mi * 16 + rA) * 80) + kb,
                       a[mi][0], a[mi][1], a[mi][2], a[mi][3]);
#pragma unroll
            for (int nj = 0; nj < 2; nj++) {
                uint32_t r0, r1, r2, r3;
                ldm_x4(sB + (uint32_t)((wn + nj * 16 + rA) * 80) + kb, r0, r1, r2, r3);
                bf[nj * 2 + 0][0] = r0; bf[nj * 2 + 1][0] = r1;
                bf[nj * 2 + 0][1] = r2; bf[nj * 2 + 1][1] = r3;
            }
#pragma unroll
            for (int mi = 0; mi < WMI; mi++)
#pragma unroll
                for (int nt = 0; nt < 4; nt++)
                    mma16816(acc[mi][nt], a[mi], bf[nt]);
        }
        int ns = kt + S - 1;
        if (ns < NK) {
            ld_tile(smu + (ns % S) * STG,       A + ns * 32, lda, BM, tid);
            ld_tile(smu + (ns % S) * STG + ASZ, B + ns * 32, ldb, BN, tid);
        }
        CP_COMMIT();
    }
    CP_WAIT(0);
    __syncthreads();

    float* esm = (float*)sm;
    const int er = lane >> 2, ec = (lane & 3) * 2;
#pragma unroll
    for (int mi = 0; mi < WMI; mi++)
#pragma unroll
        for (int nt = 0; nt < 4; nt++) {
            int r0 = wm + mi * 16 + er;
            int c0 = wn + nt * 8 + ec;
            *(float2*)&esm[(size_t)r0 * BN + c0]       = make_float2(acc[mi][nt][0], acc[mi][nt][1]);
            *(float2*)&esm[(size_t)(r0 + 8) * BN + c0] = make_float2(acc[mi][nt][2], acc[mi][nt][3]);
        }
    __syncthreads();

    for (int ci = tid; ci < BM * BN / 4; ci += 256) {
        int r  = ci / (BN / 4);
        int c0 = (ci % (BN / 4)) * 4;
        float4 v = *(const float4*)&esm[(size_t)r * BN + c0];
        int m = bm + r;
        if (MODE == 0) {
            int e0 = bn + c0;
            float4 o = make_float4(v.x + bias[e0], v.y + bias[e0+1],
                                   v.z + bias[e0+2], v.w + bias[e0+3]);
            *(float4*)&outF[(size_t)m * DD + e0] = o;
        } else if (MODE == 1) {
            int e0 = bn + c0;
            int h = e0 >> 6, dk0 = e0 & 63;
            int bb = m >> 11, s = m & (SS - 1);
            __half2 h0 = __floats2half2_rn(v.x + bias[e0],   v.y + bias[e0+1]);
            __half2 h1 = __floats2half2_rn(v.z + bias[e0+2], v.w + bias[e0+3]);
            __half2* dst = (__half2*)&outH[(((size_t)(bb * HH + h)) * SS + s) * DK + dk0];
            dst[0] = h0; dst[1] = h1;
        } else if (MODE == 2) {
            int e0 = bn + c0;
            int bb = m >> 11, s = m & (SS - 1);
            float vv[4] = {v.x, v.y, v.z, v.w};
#pragma unroll
            for (int j = 0; j < 4; j++) {
                int e = e0 + j;
                int h = e >> 6, dk = e & 63;
                outH[((size_t)(bb * HH + h) * DK + dk) * SS + s] = __float2half_rn(vv[j] + bias[e]);
            }
        } else { // MODE 4: ctx half (b,s,d); m = q-row within (b,h) matrix, z = b*HH+h
            int bb = z >> 4, h = z & 15;
            __half2 h0 = __floats2half2_rn(v.x, v.y);
            __half2 h1 = __floats2half2_rn(v.z, v.w);
            __half2* dst = (__half2*)&outH[((size_t)bb * SS + m) * DD + h * DK + bn + c0];
            dst[0] = h0; dst[1] = h1;
        }
    }
}

// ============================================================================
// Fused scores + softmax (flash-style 2-pass with recompute).
// ============================================================================
#define QO 0
#define KO 20480
#define EO 61440                 // half esm16[128][136]
#define MO 96256                 // float s_m[128]
#define SO 96768                 // float s_s[128]
#define RO 97280                 // float s_red[4][128]  (reused as s_inv)
#define SSM_BYTES 99456

__global__ __launch_bounds__(256) void tc_ssm(
    const __half* __restrict__ qh, const __half* __restrict__ kh,
    const int* __restrict__ mask, float* __restrict__ P, __half* __restrict__ P16)
{
    extern __shared__ char smraw[];
    char* sm = (char*)(((uintptr_t)smraw + 127) & ~(uintptr_t)127);
    uint32_t smu = smem_u32(sm);

    const int tid = threadIdx.x;
    const int w = tid >> 5, lane = tid & 31;
    const int bq = blockIdx.x * 128;
    const int z  = blockIdx.y;
    const int bb = z >> 4;

    const __half* Qg = qh + (size_t)z * SS * DK + (size_t)bq * DK;
    const __half* Kg = kh + (size_t)z * SS * DK;

    const int wm = (w >> 2) * 64;
    const int wn = (w & 3) * 32;
    const int nw = w & 3;
    const int rA = (lane & 7) + ((lane >> 3) & 1) * 8;
    const int kO = ((lane >> 4) << 3) * 2;
    const int er = lane >> 2, ec = (lane & 3) * 2;

    float*  s_m   = (float*)(sm + MO);
    float*  s_s   = (float*)(sm + SO);
    float*  s_red = (float*)(sm + RO);
    __half* e16   = (__half*)(sm + EO);

    ld_tile64(smu + QO, Qg, tid);
    ld_tile64(smu + KO, Kg, tid);
    CP_COMMIT();
    if (tid < 128) { s_m[tid] = -INFINITY; s_s[tid] = 0.f; }

    uint32_t qf[2][2][4][4];
    {
        CP_WAIT(0);
        __syncthreads();
#pragma unroll
        for (int ch = 0; ch < 2; ch++)
#pragma unroll
            for (int ks = 0; ks < 2; ks++)
#pragma unroll
                for (int mi = 0; mi < 4; mi++)
                    ldm_x4(smu + QO + (uint32_t)(ch * 10240 + (wm + mi * 16 + rA) * 80 + ks * 32 + kO),
                           qf[ch][ks][mi][0], qf[ch][ks][mi][1], qf[ch][ks][mi][2], qf[ch][ks][mi][3]);
    }

    // ======================= PASS A =======================
    for (int j = 0; j < 16; j++) {
        if (j > 0) { CP_WAIT(0); }
        __syncthreads();
        if (j < 15) { ld_tile64(smu + KO + ((j + 1) & 1) * 20480, Kg + (size_t)(j + 1) * 128 * DK, tid); CP_COMMIT(); }

        float acc[4][4][4];
#pragma unroll
        for (int mi = 0; mi < 4; mi++)
#pragma unroll
            for (int nt = 0; nt < 4; nt++)
#pragma unroll
                for (int x = 0; x < 4; x++) acc[mi][nt][x] = 0.f;

        uint32_t kbase = smu + KO + (uint32_t)((j & 1) * 20480);
#pragma unroll
        for (int ch = 0; ch < 2; ch++)
#pragma unroll
            for (int ks = 0; ks < 2; ks++) {
                uint32_t kb = (uint32_t)(ks * 32 + kO);
                uint32_t bf[4][2];
#pragma unroll
                for (int nj = 0; nj < 2; nj++) {
                    uint32_t r0, r1, r2, r3;
                    ldm_x4(kbase + (uint32_t)(ch * 10240 + (wn + nj * 16 + rA) * 80) + kb, r0, r1, r2, r3);
                    bf[nj * 2 + 0][0] = r0; bf[nj * 2 + 1][0] = r1;
                    bf[nj * 2 + 0][1] = r2; bf[nj * 2 + 1][1] = r3;
                }
#pragma unroll
                for (int mi = 0; mi < 4; mi++)
#pragma unroll
                    for (int nt = 0; nt < 4; nt++)
                        mma16816(acc[mi][nt], qf[ch][ks][mi], bf[nt]);
            }

        const int jc = j * 128;
#pragma unroll
        for (int mi = 0; mi < 4; mi++)
#pragma unroll
            for (int hx = 0; hx < 2; hx++) {
                int row = wm + mi * 16 + er + hx * 8;
                const int* mrowp = mask + ((size_t)(bb * SS + bq + row)) * SS + jc + wn + ec;
#pragma unroll
                for (int nt = 0; nt < 4; nt++) {
                    int2 mm = *(const int2*)(mrowp + nt * 8);
                    acc[mi][nt][hx*2+0] = mm.x ? acc[mi][nt][hx*2+0] * 0.125f : NEGV;
                    acc[mi][nt][hx*2+1] = mm.y ? acc[mi][nt][hx*2+1] * 0.125f : NEGV;
                }
            }

        float pm[4][2];
#pragma unroll
        for (int mi = 0; mi < 4; mi++)
#pragma unroll
            for (int hx = 0; hx < 2; hx++) {
                float v = fmaxf(acc[mi][0][hx*2], acc[mi][0][hx*2+1]);
#pragma unroll
                for (int nt = 1; nt < 4; nt++)
                    v = fmaxf(v, fmaxf(acc[mi][nt][hx*2], acc[mi][nt][hx*2+1]));
                v = fmaxf(v, __shfl_xor_sync(~0u, v, 1));
                v = fmaxf(v, __shfl_xor_sync(~0u, v, 2));
                pm[mi][hx] = v;
            }
        if ((lane & 3) == 0)
#pragma unroll
            for (int mi = 0; mi < 4; mi++)
#pragma unroll
                for (int hx = 0; hx < 2; hx++)
                    s_red[nw * 128 + wm + mi * 16 + er + hx * 8] = pm[mi][hx];
        __syncthreads();
        if (tid < 128) {
            float tm = fmaxf(fmaxf(s_red[tid], s_red[128 + tid]),
                             fmaxf(s_red[256 + tid], s_red[384 + tid]));
            float om = s_m[tid];
            float nm = fmaxf(om, tm);
            s_s[tid] *= __expf(om - nm);
            s_m[tid] = nm;
        }
        __syncthreads();

        float ps[4][2];
#pragma unroll
        for (int mi = 0; mi < 4; mi++)
#pragma unroll
            for (int hx = 0; hx < 2; hx++) {
                int row = wm + mi * 16 + er + hx * 8;
                float mr = s_m[row];
                float v = 0.f;
#pragma unroll
                for (int nt = 0; nt < 4; nt++)
                    v += __expf(acc[mi][nt][hx*2] - mr) + __expf(acc[mi][nt][hx*2+1] - mr);
                v += __shfl_xor_sync(~0u, v, 1);
                v += __shfl_xor_sync(~0u, v, 2);
                ps[mi][hx] = v;
            }
        if ((lane & 3) == 0)
#pragma unroll
            for (int mi = 0; mi < 4; mi++)
#pragma unroll
                for (int hx = 0; hx < 2; hx++)
                    s_red[nw * 128 + wm + mi * 16 + er + hx * 8] = ps[mi][hx];
        __syncthreads();
        if (tid < 128)
            s_s[tid] += s_red[tid] + s_red[128 + tid] + s_red[256 + tid] + s_red[384 + tid];
    }

    __syncthreads();
    if (tid < 128) s_red[tid] = 1.0f / s_s[tid];   // s_inv
    ld_tile64(smu + KO, Kg, tid);
    CP_COMMIT();

    // ======================= PASS B =======================
    float* s_inv = s_red;
    float* Pz = P + (size_t)z * SS * SS;
    __half* Pz16 = P16 + (size_t)z * SS * SS;
    for (int j = 0; j < 16; j++) {
        CP_WAIT(0);
        __syncthreads();
        if (j < 15) { ld_tile64(smu + KO + ((j + 1) & 1) * 20480, Kg + (size_t)(j + 1) * 128 * DK, tid); CP_COMMIT(); }

        float acc[4][4][4];
#pragma unroll
        for (int mi = 0; mi < 4; mi++)
#pragma unroll
            for (int nt = 0; nt < 4; nt++)
#pragma unroll
                for (int x = 0; x < 4; x++) acc[mi][nt][x] = 0.f;

        uint32_t kbase = smu + KO + (uint32_t)((j & 1) * 20480);
#pragma unroll
        for (int ch = 0; ch < 2; ch++)
#pragma unroll
            for (int ks = 0; ks < 2; ks++) {
                uint32_t kb = (uint32_t)(ks * 32 + kO);
                uint32_t bf[4][2];
#pragma unroll
                for (int nj = 0; nj < 2; nj++) {
                    uint32_t r0, r1, r2, r3;
                    ldm_x4(kbase + (uint32_t)(ch * 10240 + (wn + nj * 16 + rA) * 80) + kb, r0, r1, r2, r3);
                    bf[nj * 2 + 0][0] = r0; bf[nj * 2 + 1][0] = r1;
                    bf[nj * 2 + 0][1] = r2; bf[nj * 2 + 1][1] = r3;
                }
#pragma unroll
                for (int mi = 0; mi < 4; mi++)
#pragma unroll
                    for (int nt = 0; nt < 4; nt++)
                        mma16816(acc[mi][nt], qf[ch][ks][mi], bf[nt]);
            }

        const int jc = j * 128;
#pragma unroll
        for (int mi = 0; mi < 4; mi++)
#pragma unroll
            for (int hx = 0; hx < 2; hx++) {
                int row = wm + mi * 16 + er + hx * 8;
                float mr = s_m[row], ir = s_inv[row];
                const int* mrowp = mask + ((size_t)(bb * SS + bq + row)) * SS + jc + wn + ec;
                float* prow = Pz + (size_t)(bq + row) * SS + jc + wn + ec;
#pragma unroll
                for (int nt = 0; nt < 4; nt++) {
                    int2 mm = *(const int2*)(mrowp + nt * 8);
                    float x0 = mm.x ? acc[mi][nt][hx*2+0] * 0.125f : NEGV;
                    float x1 = mm.y ? acc[mi][nt][hx*2+1] * 0.125f : NEGV;
                    float p0 = __expf(x0 - mr) * ir;
                    float p1 = __expf(x1 - mr) * ir;
                    *(float2*)(prow + nt * 8) = make_float2(p0, p1);
                    *(__half2*)&e16[row * 136 + wn + nt * 8 + ec] = __floats2half2_rn(p0, p1);
                }
            }
        __syncthreads();
#pragma unroll
        for (int i = 0; i < 8; i++) {
            int idx = tid + i * 256;
            int r = idx >> 4, c8 = (idx & 15) * 8;
            uint4 v = *(const uint4*)&e16[r * 136 + c8];
            *(uint4*)&Pz16[(size_t)(bq + r) * SS + jc + c8] = v;
        }
    }
}

// ======================= fp32 -> fp16 convert =======================
__global__ __launch_bounds__(256) void k_f2h(const float* __restrict__ x,
                                             __half* __restrict__ y)
{
    size_t i = ((size_t)blockIdx.x * 256 + threadIdx.x) * 4;
    float4 v = *(const float4*)(x + i);
    *(__half2*)(y + i)     = __floats2half2_rn(v.x, v.y);
    *(__half2*)(y + i + 2) = __floats2half2_rn(v.z, v.w);
}

// ======================= launch =======================
extern "C" void kernel_launch(void* const* d_in, const int* in_sizes, int n_in,
                              void* d_out, int out_size)
{
    const float* q    = (const float*)d_in[0];
    const float* k    = (const float*)d_in[1];
    const float* v    = (const float*)d_in[2];
    const int*   mask = (const int*)  d_in[3];
    const float* Wq   = (const float*)d_in[4];
    const float* bq_  = (const float*)d_in[5];
    const float* Wk   = (const float*)d_in[6];
    const float* bk_  = (const float*)d_in[7];
    const float* Wv   = (const float*)d_in[8];
    const float* bv_  = (const float*)d_in[9];
    const float* Wo   = (const float*)d_in[10];
    const float* bo_  = (const float*)d_in[11];
    float* out = (float*)d_out;

    const long long out_elems = (long long)MROWS * DD;
    const long long p_elems   = (long long)BB * HH * SS * SS;

    float* p_base;
    if ((long long)out_size >= out_elems + p_elems) {
        p_base = out + out_elems;
    } else {
        void* sp = nullptr;
        cudaGetSymbolAddress(&sp, g_pattn_scratch);
        p_base = (float*)sp;
    }

    void *pa16, *pw16, *pqh, *pkh, *pvt, *pp16;
    cudaGetSymbolAddress(&pa16, g_a16);
    cudaGetSymbolAddress(&pw16, g_w16);
    cudaGetSymbolAddress(&pqh,  g_qh16);
    cudaGetSymbolAddress(&pkh,  g_kh16);
    cudaGetSymbolAddress(&pvt,  g_vt16);
    cudaGetSymbolAddress(&pp16, g_p16);
    __half* a16 = (__half*)pa16;
    __half* w16 = (__half*)pw16;
    __half* qh16 = (__half*)pqh;
    __half* kh16 = (__half*)pkh;
    __half* vt16 = (__half*)pvt;
    __half* p16  = (__half*)pp16;

    const int SM_MAIN = 82048;    // proj: 4 stages * (128+128)*80
    const int SM_AV   = 102528;   // AV:   4 stages * (256+64)*80
    cudaFuncSetAttribute(tc_mm<4,4,0>, cudaFuncAttributeMaxDynamicSharedMemorySize, SM_MAIN);
    cudaFuncSetAttribute(tc_mm<4,4,1>, cudaFuncAttributeMaxDynamicSharedMemorySize, SM_MAIN);
    cudaFuncSetAttribute(tc_mm<4,4,2>, cudaFuncAttributeMaxDynamicSharedMemorySize, SM_MAIN);
    cudaFuncSetAttribute(tc_mm<2,4,4>, cudaFuncAttributeMaxDynamicSharedMemorySize, SM_AV);
    cudaFuncSetAttribute(tc_ssm,       cudaFuncAttributeMaxDynamicSharedMemorySize, SSM_BYTES);

    const int nIn = MROWS * DD / 1024;
    const int nW  = DD * DD / 1024;

    dim3 gProj(DD / 128, MROWS / 128, 1);       // (8,32)
    k_f2h<<<nIn, 256>>>(q, a16);
    k_f2h<<<nW, 256>>>(Wq, w16);
    tc_mm<4,4,1><<<gProj, 256, SM_MAIN>>>(a16, DD, 0, w16, DD, 0, DD, bq_, nullptr, qh16);
    k_f2h<<<nIn, 256>>>(k, a16);
    k_f2h<<<nW, 256>>>(Wk, w16);
    tc_mm<4,4,1><<<gProj, 256, SM_MAIN>>>(a16, DD, 0, w16, DD, 0, DD, bk_, nullptr, kh16);
    k_f2h<<<nIn, 256>>>(v, a16);
    k_f2h<<<nW, 256>>>(Wv, w16);
    tc_mm<4,4,2><<<gProj, 256, SM_MAIN>>>(a16, DD, 0, w16, DD, 0, DD, bv_, nullptr, vt16);

    // fused scores + softmax
    dim3 gSSM(SS / 128, BB * HH);               // (16,32)
    tc_ssm<<<gSSM, 256, SSM_BYTES>>>(qh16, kh16, mask, p_base, p16);

    // AV: ctx = P @ Vt^T   (BM=256, BN=64)
    dim3 gAV(1, SS / 256, BB * HH);             // (1,8,32)
    tc_mm<2,4,4><<<gAV, 256, SM_AV>>>(p16, SS, (size_t)SS * SS,
                                      vt16, SS, (size_t)DK * SS, SS,
                                      nullptr, nullptr, a16);

    // output projection
    k_f2h<<<nW, 256>>>(Wo, w16);
    tc_mm<4,4,0><<<gProj, 256, SM_MAIN>>>(a16, DD, 0, w16, DD, 0, DD, bo_, out, nullptr);
}

// round 7
// speedup vs baseline: 1.1504x; 1.1504x over previous
#include <cuda_runtime.h>
#include <cuda_fp16.h>
#include <cstdint>

#define BB 2
#define SS 2048
#define DD 1024
#define HH 16
#define DK 64
#define MROWS (BB*SS)
#define NEGV -1000000000.0f

// ---------------- scratch ----------------
__device__ __align__(128) __half g_a16[(size_t)MROWS*DD];
__device__ __align__(128) __half g_w16[(size_t)DD*DD];
__device__ __align__(128) __half g_qh16[(size_t)BB*HH*SS*DK];  // (z,s,dk)
__device__ __align__(128) __half g_kh16[(size_t)BB*HH*SS*DK];  // (z,s,dk)
__device__ __align__(128) __half g_vt16[(size_t)BB*HH*DK*SS];  // (z,dk,s)
__device__ __align__(128) __half g_p16[(size_t)BB*HH*SS*SS];   // fp16 p_attn
__device__ float g_pattn_scratch[(size_t)BB*HH*SS*SS];         // fallback

// ---------------- helpers ----------------
__device__ __forceinline__ uint32_t smem_u32(const void* p) {
    uint32_t a;
    asm("{ .reg .u64 t; cvta.to.shared.u64 t, %1; cvt.u32.u64 %0, t; }" : "=r"(a) : "l"(p));
    return a;
}

#define CP_ASYNC16(dst, src) \
    asm volatile("cp.async.cg.shared.global [%0], [%1], 16;" :: "r"(dst), "l"(src) : "memory")
#define CP_COMMIT() asm volatile("cp.async.commit_group;" ::: "memory")
#define CP_WAIT(n)  asm volatile("cp.async.wait_group %0;" :: "n"(n) : "memory")

__device__ __forceinline__ void ldm_x4(uint32_t addr, uint32_t& r0, uint32_t& r1,
                                       uint32_t& r2, uint32_t& r3) {
    asm volatile("ldmatrix.sync.aligned.m8n8.x4.shared.b16 {%0,%1,%2,%3}, [%4];"
                 : "=r"(r0), "=r"(r1), "=r"(r2), "=r"(r3) : "r"(addr));
}

__device__ __forceinline__ void mma16816(float* c, const uint32_t* a, const uint32_t* b) {
    asm volatile("mma.sync.aligned.m16n8k16.row.col.f32.f16.f16.f32 "
                 "{%0,%1,%2,%3},{%4,%5,%6,%7},{%8,%9},{%0,%1,%2,%3};"
                 : "+f"(c[0]), "+f"(c[1]), "+f"(c[2]), "+f"(c[3])
                 : "r"(a[0]), "r"(a[1]), "r"(a[2]), "r"(a[3]), "r"(b[0]), "r"(b[1]));
}

// (rows x 32 half) tile, 80B padded rows, NT threads
template<int NT>
__device__ __forceinline__ void ld_tileT(uint32_t dst, const __half* g, int ldh,
                                         int rows, int tid) {
    for (int ci = tid; ci < rows * 4; ci += NT) {
        int r = ci >> 2, c = ci & 3;
        CP_ASYNC16(dst + (uint32_t)(r * 80 + c * 16), g + (size_t)r * ldh + c * 8);
    }
}

// ============================================================================
// fp16 MMA GEMM, 512 threads / 16 warps, warp tile (WMI*16) x (WNI*8).
// C[BM,BN] = A[BM,K] @ B[BN,K]^T  (both K-major halves)
// MODE: 0 proj->fp32 flat +bias | 1 proj->half (z,s,dk) +bias
//       2 proj->half (z,dk,s) +bias | 3 scores masked fp32 | 4 AV ctx half
// ============================================================================
template<int WARPS_M, int WARPS_N, int WMI, int WNI, int MODE>
__global__ __launch_bounds__(512) void tc_mm(
    const __half* __restrict__ A, int lda, size_t aZ,
    const __half* __restrict__ B, int ldb, size_t bZ,
    int K,
    const float* __restrict__ bias,
    const int*   __restrict__ mask,
    float* __restrict__ outF,
    __half* __restrict__ outH)
{
    constexpr int BM  = WARPS_M * WMI * 16;
    constexpr int BN  = WARPS_N * WNI * 8;
    constexpr int ASZ = BM * 80;
    constexpr int BSZ = BN * 80;
    constexpr int STG = ASZ + BSZ;
    constexpr int S   = 4;
    constexpr int NJ  = WNI / 2;
    constexpr int NT  = 512;

    extern __shared__ char smraw[];
    char* sm = (char*)(((uintptr_t)smraw + 127) & ~(uintptr_t)127);
    uint32_t smu = smem_u32(sm);

    const int tid  = threadIdx.x;
    const int w    = tid >> 5, lane = tid & 31;
    const int bn   = blockIdx.x * BN, bm = blockIdx.y * BM;
    const int z    = blockIdx.z;

    A += (size_t)z * aZ + (size_t)bm * lda;
    B += (size_t)z * bZ + (size_t)bn * ldb;

    const int wm = (w / WARPS_N) * (WMI * 16);
    const int wn = (w % WARPS_N) * (WNI * 8);

    float acc[WMI][WNI][4];
#pragma unroll
    for (int mi = 0; mi < WMI; mi++)
#pragma unroll
        for (int nt = 0; nt < WNI; nt++)
#pragma unroll
            for (int x = 0; x < 4; x++) acc[mi][nt][x] = 0.f;

    const int NK = K / 32;
#pragma unroll
    for (int s = 0; s < S - 1; s++) {
        if (s < NK) {
            ld_tileT<NT>(smu + s * STG,       A + s * 32, lda, BM, tid);
            ld_tileT<NT>(smu + s * STG + ASZ, B + s * 32, ldb, BN, tid);
        }
        CP_COMMIT();
    }

    const int rA = (lane & 7) + ((lane >> 3) & 1) * 8;
    const int kO = ((lane >> 4) << 3) * 2;

    for (int kt = 0; kt < NK; kt++) {
        CP_WAIT(S - 2);
        __syncthreads();
        uint32_t sA = smu + (kt % S) * STG;
        uint32_t sB = sA + ASZ;
#pragma unroll
        for (int ks = 0; ks < 2; ks++) {
            uint32_t a[WMI][4], bf[WNI][2];
            uint32_t kb = (uint32_t)(ks * 32 + kO);
#pragma unroll
            for (int mi = 0; mi < WMI; mi++)
                ldm_x4(sA + (uint32_t)((wm + mi * 16 + rA) * 80) + kb,
                       a[mi][0], a[mi][1], a[mi][2], a[mi][3]);
#pragma unroll
            for (int nj = 0; nj < NJ; nj++) {
                uint32_t r0, r1, r2, r3;
                ldm_x4(sB + (uint32_t)((wn + nj * 16 + rA) * 80) + kb, r0, r1, r2, r3);
                bf[nj * 2 + 0][0] = r0; bf[nj * 2 + 1][0] = r1;
                bf[nj * 2 + 0][1] = r2; bf[nj * 2 + 1][1] = r3;
            }
#pragma unroll
            for (int mi = 0; mi < WMI; mi++)
#pragma unroll
                for (int nt = 0; nt < WNI; nt++)
                    mma16816(acc[mi][nt], a[mi], bf[nt]);
        }
        int ns = kt + S - 1;
        if (ns < NK) {
            ld_tileT<NT>(smu + (ns % S) * STG,       A + ns * 32, lda, BM, tid);
            ld_tileT<NT>(smu + (ns % S) * STG + ASZ, B + ns * 32, ldb, BN, tid);
        }
        CP_COMMIT();
    }
    CP_WAIT(0);
    __syncthreads();

    // ---- stage accumulators through smem for coalesced writes ----
    float* esm = (float*)sm;
    const int er = lane >> 2, ec = (lane & 3) * 2;
#pragma unroll
    for (int mi = 0; mi < WMI; mi++)
#pragma unroll
        for (int nt = 0; nt < WNI; nt++) {
            int r0 = wm + mi * 16 + er;
            int c0 = wn + nt * 8 + ec;
            *(float2*)&esm[(size_t)r0 * BN + c0]       = make_float2(acc[mi][nt][0], acc[mi][nt][1]);
            *(float2*)&esm[(size_t)(r0 + 8) * BN + c0] = make_float2(acc[mi][nt][2], acc[mi][nt][3]);
        }
    __syncthreads();

    for (int ci = tid; ci < BM * BN / 4; ci += NT) {
        int r  = ci / (BN / 4);
        int c0 = (ci % (BN / 4)) * 4;
        float4 v = *(const float4*)&esm[(size_t)r * BN + c0];
        int m = bm + r;
        if (MODE == 0) {
            int e0 = bn + c0;
            float4 o = make_float4(v.x + bias[e0], v.y + bias[e0+1],
                                   v.z + bias[e0+2], v.w + bias[e0+3]);
            *(float4*)&outF[(size_t)m * DD + e0] = o;
        } else if (MODE == 1) {
            int e0 = bn + c0;
            int h = e0 >> 6, dk0 = e0 & 63;
            int bb = m >> 11, s = m & (SS - 1);
            __half2 h0 = __floats2half2_rn(v.x + bias[e0],   v.y + bias[e0+1]);
            __half2 h1 = __floats2half2_rn(v.z + bias[e0+2], v.w + bias[e0+3]);
            __half2* dst = (__half2*)&outH[(((size_t)(bb * HH + h)) * SS + s) * DK + dk0];
            dst[0] = h0; dst[1] = h1;
        } else if (MODE == 2) {
            int e0 = bn + c0;
            int bb = m >> 11, s = m & (SS - 1);
            float vv[4] = {v.x, v.y, v.z, v.w};
#pragma unroll
            for (int j = 0; j < 4; j++) {
                int e = e0 + j;
                int h = e >> 6, dk = e & 63;
                outH[((size_t)(bb * HH + h) * DK + dk) * SS + s] = __float2half_rn(vv[j] + bias[e]);
            }
        } else if (MODE == 3) {
            int col0 = bn + c0;
            int bb = z >> 4;
            int4 mm = *(const int4*)&mask[((size_t)bb * SS + m) * SS + col0];
            float4 o;
            o.x = mm.x ? v.x * 0.125f : NEGV;
            o.y = mm.y ? v.y * 0.125f : NEGV;
            o.z = mm.z ? v.z * 0.125f : NEGV;
            o.w = mm.w ? v.w * 0.125f : NEGV;
            *(float4*)&outF[(size_t)z * SS * SS + (size_t)m * SS + col0] = o;
        } else { // MODE 4: ctx half (b,s,d); m = local q-row, z = b*HH+h
            int bb = z >> 4, h = z & 15;
            __half2 h0 = __floats2half2_rn(v.x, v.y);
            __half2 h1 = __floats2half2_rn(v.z, v.w);
            __half2* dst = (__half2*)&outH[((size_t)bb * SS + m) * DD + h * DK + bn + c0];
            dst[0] = h0; dst[1] = h1;
        }
    }
}

// ======================= fp32 -> fp16 convert =======================
__global__ __launch_bounds__(256) void k_f2h(const float* __restrict__ x,
                                             __half* __restrict__ y)
{
    size_t i = ((size_t)blockIdx.x * 256 + threadIdx.x) * 4;
    float4 v = *(const float4*)(x + i);
    *(__half2*)(y + i)     = __floats2half2_rn(v.x, v.y);
    *(__half2*)(y + i + 2) = __floats2half2_rn(v.z, v.w);
}

// ======================= softmax: fp32 in-place + fp16 copy =======================
__global__ __launch_bounds__(256) void k_softmax(float* __restrict__ P,
                                                 __half* __restrict__ P16)
{
    __shared__ float red[8];
    const size_t row = blockIdx.x;
    float* p = P + row * SS;
    __half* p16 = P16 + row * SS;
    const int tid = threadIdx.x;

    float4 v0 = ((const float4*)p)[tid];
    float4 v1 = ((const float4*)p)[tid + 256];

    float m = fmaxf(fmaxf(fmaxf(v0.x, v0.y), fmaxf(v0.z, v0.w)),
                    fmaxf(fmaxf(v1.x, v1.y), fmaxf(v1.z, v1.w)));
#pragma unroll
    for (int o = 16; o; o >>= 1) m = fmaxf(m, __shfl_xor_sync(~0u, m, o));
    if ((tid & 31) == 0) red[tid >> 5] = m;
    __syncthreads();
    m = red[0];
#pragma unroll
    for (int i = 1; i < 8; i++) m = fmaxf(m, red[i]);
    __syncthreads();

    float4 e0, e1;
    e0.x = __expf(v0.x - m); e0.y = __expf(v0.y - m);
    e0.z = __expf(v0.z - m); e0.w = __expf(v0.w - m);
    e1.x = __expf(v1.x - m); e1.y = __expf(v1.y - m);
    e1.z = __expf(v1.z - m); e1.w = __expf(v1.w - m);
    float s = (e0.x + e0.y) + (e0.z + e0.w) + (e1.x + e1.y) + (e1.z + e1.w);
#pragma unroll
    for (int o = 16; o; o >>= 1) s += __shfl_xor_sync(~0u, s, o);
    if ((tid & 31) == 0) red[tid >> 5] = s;
    __syncthreads();
    s = red[0];
#pragma unroll
    for (int i = 1; i < 8; i++) s += red[i];
    float inv = 1.0f / s;

    e0.x *= inv; e0.y *= inv; e0.z *= inv; e0.w *= inv;
    e1.x *= inv; e1.y *= inv; e1.z *= inv; e1.w *= inv;
    ((float4*)p)[tid]       = e0;
    ((float4*)p)[tid + 256] = e1;
    __half2* ph = (__half2*)p16;
    ph[tid * 2 + 0]   = __floats2half2_rn(e0.x, e0.y);
    ph[tid * 2 + 1]   = __floats2half2_rn(e0.z, e0.w);
    ph[512 + tid * 2] = __floats2half2_rn(e1.x, e1.y);
    ph[513 + tid * 2] = __floats2half2_rn(e1.z, e1.w);
}

// ======================= launch =======================
extern "C" void kernel_launch(void* const* d_in, const int* in_sizes, int n_in,
                              void* d_out, int out_size)
{
    const float* q    = (const float*)d_in[0];
    const float* k    = (const float*)d_in[1];
    const float* v    = (const float*)d_in[2];
    const int*   mask = (const int*)  d_in[3];
    const float* Wq   = (const float*)d_in[4];
    const float* bq_  = (const float*)d_in[5];
    const float* Wk   = (const float*)d_in[6];
    const float* bk_  = (const float*)d_in[7];
    const float* Wv   = (const float*)d_in[8];
    const float* bv_  = (const float*)d_in[9];
    const float* Wo   = (const float*)d_in[10];
    const float* bo_  = (const float*)d_in[11];
    float* out = (float*)d_out;

    const long long out_elems = (long long)MROWS * DD;
    const long long p_elems   = (long long)BB * HH * SS * SS;

    float* p_base;
    if ((long long)out_size >= out_elems + p_elems) {
        p_base = out + out_elems;
    } else {
        void* sp = nullptr;
        cudaGetSymbolAddress(&sp, g_pattn_scratch);
        p_base = (float*)sp;
    }

    void *pa16, *pw16, *pqh, *pkh, *pvt, *pp16;
    cudaGetSymbolAddress(&pa16, g_a16);
    cudaGetSymbolAddress(&pw16, g_w16);
    cudaGetSymbolAddress(&pqh,  g_qh16);
    cudaGetSymbolAddress(&pkh,  g_kh16);
    cudaGetSymbolAddress(&pvt,  g_vt16);
    cudaGetSymbolAddress(&pp16, g_p16);
    __half* a16 = (__half*)pa16;
    __half* w16 = (__half*)pw16;
    __half* qh16 = (__half*)pqh;
    __half* kh16 = (__half*)pkh;
    __half* vt16 = (__half*)pvt;
    __half* p16  = (__half*)pp16;

    const int SM_MAIN = 82048;    // 4 stages * (128+128)*80 + align
    const int SM_AV   = 102528;   // 4 stages * (256+64)*80 + align
    cudaFuncSetAttribute(tc_mm<4,4,2,4,0>, cudaFuncAttributeMaxDynamicSharedMemorySize, SM_MAIN);
    cudaFuncSetAttribute(tc_mm<4,4,2,4,1>, cudaFuncAttributeMaxDynamicSharedMemorySize, SM_MAIN);
    cudaFuncSetAttribute(tc_mm<4,4,2,4,2>, cudaFuncAttributeMaxDynamicSharedMemorySize, SM_MAIN);
    cudaFuncSetAttribute(tc_mm<4,4,2,4,3>, cudaFuncAttributeMaxDynamicSharedMemorySize, SM_MAIN);
    cudaFuncSetAttribute(tc_mm<8,2,2,4,4>, cudaFuncAttributeMaxDynamicSharedMemorySize, SM_AV);

    const int nIn = MROWS * DD / 1024;
    const int nW  = DD * DD / 1024;

    dim3 gProj(DD / 128, MROWS / 128, 1);       // (8,32)
    k_f2h<<<nIn, 256>>>(q, a16);
    k_f2h<<<nW, 256>>>(Wq, w16);
    tc_mm<4,4,2,4,1><<<gProj, 512, SM_MAIN>>>(a16, DD, 0, w16, DD, 0, DD,
                                              bq_, nullptr, nullptr, qh16);
    k_f2h<<<nIn, 256>>>(k, a16);
    k_f2h<<<nW, 256>>>(Wk, w16);
    tc_mm<4,4,2,4,1><<<gProj, 512, SM_MAIN>>>(a16, DD, 0, w16, DD, 0, DD,
                                              bk_, nullptr, nullptr, kh16);
    k_f2h<<<nIn, 256>>>(v, a16);
    k_f2h<<<nW, 256>>>(Wv, w16);
    tc_mm<4,4,2,4,2><<<gProj, 512, SM_MAIN>>>(a16, DD, 0, w16, DD, 0, DD,
                                              bv_, nullptr, nullptr, vt16);

    // scores (raw masked scaled) -> fp32 P
    dim3 gScores(SS / 128, SS / 128, BB * HH);  // (16,16,32)
    tc_mm<4,4,2,4,3><<<gScores, 512, SM_MAIN>>>(qh16, DK, (size_t)SS * DK,
                                                kh16, DK, (size_t)SS * DK, DK,
                                                nullptr, mask, p_base, nullptr);

    // softmax in-place + fp16 copy
    k_softmax<<<BB * HH * SS, 256>>>(p_base, p16);

    // AV: ctx = P @ Vt^T   (BM=256, BN=64)
    dim3 gAV(1, SS / 256, BB * HH);             // (1,8,32)
    tc_mm<8,2,2,4,4><<<gAV, 512, SM_AV>>>(p16, SS, (size_t)SS * SS,
                                          vt16, SS, (size_t)DK * SS, SS,
                                          nullptr, nullptr, nullptr, a16);

    // output projection
    k_f2h<<<nW, 256>>>(Wo, w16);
    tc_mm<4,4,2,4,0><<<gProj, 512, SM_MAIN>>>(a16, DD, 0, w16, DD, 0, DD,
                                              bo_, nullptr, out, nullptr);
}

// round 9
// speedup vs baseline: 1.1765x; 1.0227x over previous
#include <cuda_runtime.h>
#include <cuda_fp16.h>
#include <cstdint>

#define BB 2
#define SS 2048
#define DD 1024
#define HH 16
#define DK 64
#define MROWS (BB*SS)
#define NEGV -1000000000.0f
#define NROWS_TOT (BB*HH*SS)     // 65536
#define NTILES 16                // 2048/128

// ---------------- scratch ----------------
__device__ __align__(128) __half g_a16[(size_t)MROWS*DD];
__device__ __align__(128) __half g_w16[(size_t)DD*DD];
__device__ __align__(128) __half g_qh16[(size_t)BB*HH*SS*DK];
__device__ __align__(128) __half g_kh16[(size_t)BB*HH*SS*DK];
__device__ __align__(128) __half g_vt16[(size_t)BB*HH*DK*SS];
__device__ __align__(128) __half g_p16[(size_t)BB*HH*SS*SS];
__device__ float g_tmax[(size_t)NROWS_TOT*NTILES];
__device__ float g_tsum[(size_t)NROWS_TOT*NTILES];
__device__ float g_gm[NROWS_TOT];
__device__ float g_ginv[NROWS_TOT];
__device__ float g_pattn_scratch[(size_t)BB*HH*SS*SS];   // fallback

// ---------------- helpers ----------------
__device__ __forceinline__ uint32_t smem_u32(const void* p) {
    uint32_t a;
    asm("{ .reg .u64 t; cvta.to.shared.u64 t, %1; cvt.u32.u64 %0, t; }" : "=r"(a) : "l"(p));
    return a;
}

#define CP_ASYNC16(dst, src) \
    asm volatile("cp.async.cg.shared.global [%0], [%1], 16;" :: "r"(dst), "l"(src) : "memory")
#define CP_COMMIT() asm volatile("cp.async.commit_group;" ::: "memory")
#define CP_WAIT(n)  asm volatile("cp.async.wait_group %0;" :: "n"(n) : "memory")

__device__ __forceinline__ void ldm_x4(uint32_t addr, uint32_t& r0, uint32_t& r1,
                                       uint32_t& r2, uint32_t& r3) {
    asm volatile("ldmatrix.sync.aligned.m8n8.x4.shared.b16 {%0,%1,%2,%3}, [%4];"
                 : "=r"(r0), "=r"(r1), "=r"(r2), "=r"(r3) : "r"(addr));
}

__device__ __forceinline__ void mma16816(float* c, const uint32_t* a, const uint32_t* b) {
    asm volatile("mma.sync.aligned.m16n8k16.row.col.f32.f16.f16.f32 "
                 "{%0,%1,%2,%3},{%4,%5,%6,%7},{%8,%9},{%0,%1,%2,%3};"
                 : "+f"(c[0]), "+f"(c[1]), "+f"(c[2]), "+f"(c[3])
                 : "r"(a[0]), "r"(a[1]), "r"(a[2]), "r"(a[3]), "r"(b[0]), "r"(b[1]));
}

// (rows x 32 half) tile, 80B padded rows, 256 threads
__device__ __forceinline__ void ld_tile(uint32_t dst, const __half* g, int ldh,
                                        int rows, int tid) {
    for (int ci = tid; ci < rows * 4; ci += 256) {
        int r = ci >> 2, c = ci & 3;
        CP_ASYNC16(dst + (uint32_t)(r * 80 + c * 16), g + (size_t)r * ldh + c * 8);
    }
}

// ============================================================================
// fp16 MMA GEMM, 256 threads / 8 warps.
// MODE: 0 proj->fp32 flat +bias | 1 proj->half (z,s,dk) +bias
//       2 proj->half (z,dk,s) +bias | 4 AV ctx half
//       5 scores stats only (max,sumexp per row-tile) | 6 scores normalize+write
// ============================================================================
template<int WARPS_M, int WARPS_N, int WMI, int WNI, int S, int MODE>
__global__ __launch_bounds__(256) void tc_mm(
    const __half* __restrict__ A, int lda, size_t aZ,
    const __half* __restrict__ B, int ldb, size_t bZ,
    int K,
    const float* __restrict__ bias,
    const int*   __restrict__ mask,
    const float* __restrict__ gm,
    const float* __restrict__ ginv,
    float* __restrict__ st_max,
    float* __restrict__ st_sum,
    float* __restrict__ outF,
    __half* __restrict__ outH)
{
    constexpr int BM  = WARPS_M * WMI * 16;
    constexpr int BN  = WARPS_N * WNI * 8;
    constexpr int ASZ = BM * 80;
    constexpr int BSZ = BN * 80;
    constexpr int STG = ASZ + BSZ;
    constexpr int NJ  = WNI / 2;

    extern __shared__ char smraw[];
    char* sm = (char*)(((uintptr_t)smraw + 127) & ~(uintptr_t)127);
    uint32_t smu = smem_u32(sm);

    const int tid  = threadIdx.x;
    const int w    = tid >> 5, lane = tid & 31;
    const int bn   = blockIdx.x * BN, bm = blockIdx.y * BM;
    const int z    = blockIdx.z;

    A += (size_t)z * aZ + (size_t)bm * lda;
    B += (size_t)z * bZ + (size_t)bn * ldb;

    const int wm = (w / WARPS_N) * (WMI * 16);
    const int wn = (w % WARPS_N) * (WNI * 8);
    const int nw = w % WARPS_N;

    float acc[WMI][WNI][4];
#pragma unroll
    for (int mi = 0; mi < WMI; mi++)
#pragma unroll
        for (int nt = 0; nt < WNI; nt++)
#pragma unroll
            for (int x = 0; x < 4; x++) acc[mi][nt][x] = 0.f;

    const int NK = K / 32;
#pragma unroll
    for (int s = 0; s < S - 1; s++) {
        if (s < NK) {
            ld_tile(smu + s * STG,       A + s * 32, lda, BM, tid);
            ld_tile(smu + s * STG + ASZ, B + s * 32, ldb, BN, tid);
        }
        CP_COMMIT();
    }

    const int rA = (lane & 7) + ((lane >> 3) & 1) * 8;
    const int kO = ((lane >> 4) << 3) * 2;
    const int er = lane >> 2, ec = (lane & 3) * 2;

    for (int kt = 0; kt < NK; kt++) {
        CP_WAIT(S - 2);
        __syncthreads();
        uint32_t sA = smu + (kt % S) * STG;
        uint32_t sB = sA + ASZ;
#pragma unroll
        for (int ks = 0; ks < 2; ks++) {
            uint32_t a[WMI][4], bf[WNI][2];
            uint32_t kb = (uint32_t)(ks * 32 + kO);
#pragma unroll
            for (int mi = 0; mi < WMI; mi++)
                ldm_x4(sA + (uint32_t)((wm + mi * 16 + rA) * 80) + kb,
                       a[mi][0], a[mi][1], a[mi][2], a[mi][3]);
#pragma unroll
            for (int nj = 0; nj < NJ; nj++) {
                uint32_t r0, r1, r2, r3;
                ldm_x4(sB + (uint32_t)((wn + nj * 16 + rA) * 80) + kb, r0, r1, r2, r3);
                bf[nj * 2 + 0][0] = r0; bf[nj * 2 + 1][0] = r1;
                bf[nj * 2 + 0][1] = r2; bf[nj * 2 + 1][1] = r3;
            }
#pragma unroll
            for (int mi = 0; mi < WMI; mi++)
#pragma unroll
                for (int nt = 0; nt < WNI; nt++)
                    mma16816(acc[mi][nt], a[mi], bf[nt]);
        }
        int ns = kt + S - 1;
        if (ns < NK) {
            ld_tile(smu + (ns % S) * STG,       A + ns * 32, lda, BM, tid);
            ld_tile(smu + (ns % S) * STG + ASZ, B + ns * 32, ldb, BN, tid);
        }
        CP_COMMIT();
    }
    CP_WAIT(0);
    __syncthreads();

    if (MODE == 5) {
        // ---- stats epilogue: mask+scale, per-row tile max & sumexp ----
        const int bb = z >> 4;
        float* s_red = (float*)(sm + S * STG);          // [WARPS_N][128]
        float* s_mx  = (float*)(sm + S * STG + 2048);   // [128]
#pragma unroll
        for (int mi = 0; mi < WMI; mi++)
#pragma unroll
            for (int hx = 0; hx < 2; hx++) {
                int row = wm + mi * 16 + er + hx * 8;
                const int* mp = mask + ((size_t)(bb * SS + bm + row)) * SS + bn + wn + ec;
#pragma unroll
                for (int nt = 0; nt < WNI; nt++) {
                    int2 mm = *(const int2*)(mp + nt * 8);
                    acc[mi][nt][hx*2+0] = mm.x ? acc[mi][nt][hx*2+0] * 0.125f : NEGV;
                    acc[mi][nt][hx*2+1] = mm.y ? acc[mi][nt][hx*2+1] * 0.125f : NEGV;
                }
            }
        // row max
#pragma unroll
        for (int mi = 0; mi < WMI; mi++)
#pragma unroll
            for (int hx = 0; hx < 2; hx++) {
                float v = fmaxf(acc[mi][0][hx*2], acc[mi][0][hx*2+1]);
#pragma unroll
                for (int nt = 1; nt < WNI; nt++)
                    v = fmaxf(v, fmaxf(acc[mi][nt][hx*2], acc[mi][nt][hx*2+1]));
                v = fmaxf(v, __shfl_xor_sync(~0u, v, 1));
                v = fmaxf(v, __shfl_xor_sync(~0u, v, 2));
                if ((lane & 3) == 0)
                    s_red[nw * 128 + wm + mi * 16 + er + hx * 8] = v;
            }
        __syncthreads();
        if (tid < 128) {
            float m4 = s_red[tid];
#pragma unroll
            for (int i = 1; i < WARPS_N; i++) m4 = fmaxf(m4, s_red[i * 128 + tid]);
            s_mx[tid] = m4;
        }
        __syncthreads();
        // row sumexp
#pragma unroll
        for (int mi = 0; mi < WMI; mi++)
#pragma unroll
            for (int hx = 0; hx < 2; hx++) {
                int row = wm + mi * 16 + er + hx * 8;
                float mr = s_mx[row];
                float v = 0.f;
#pragma unroll
                for (int nt = 0; nt < WNI; nt++)
                    v += __expf(acc[mi][nt][hx*2] - mr) + __expf(acc[mi][nt][hx*2+1] - mr);
                v += __shfl_xor_sync(~0u, v, 1);
                v += __shfl_xor_sync(~0u, v, 2);
                if ((lane & 3) == 0)
                    s_red[nw * 128 + wm + mi * 16 + er + hx * 8] = v;
            }
        __syncthreads();
        if (tid < 128) {
            float S4 = s_red[tid];
#pragma unroll
            for (int i = 1; i < WARPS_N; i++) S4 += s_red[i * 128 + tid];
            size_t grow = (size_t)z * SS + bm + tid;
            st_max[grow * NTILES + blockIdx.x] = s_mx[tid];
            st_sum[grow * NTILES + blockIdx.x] = S4;
        }
        return;
    }

    // ---- stage accumulators through smem ----
    float* esm = (float*)sm;
#pragma unroll
    for (int mi = 0; mi < WMI; mi++)
#pragma unroll
        for (int nt = 0; nt < WNI; nt++) {
            int r0 = wm + mi * 16 + er;
            int c0 = wn + nt * 8 + ec;
            *(float2*)&esm[(size_t)r0 * BN + c0]       = make_float2(acc[mi][nt][0], acc[mi][nt][1]);
            *(float2*)&esm[(size_t)(r0 + 8) * BN + c0] = make_float2(acc[mi][nt][2], acc[mi][nt][3]);
        }
    __syncthreads();

    for (int ci = tid; ci < BM * BN / 4; ci += 256) {
        int r  = ci / (BN / 4);
        int c0 = (ci % (BN / 4)) * 4;
        float4 v = *(const float4*)&esm[(size_t)r * BN + c0];
        int m = bm + r;
        if (MODE == 0) {
            int e0 = bn + c0;
            float4 o = make_float4(v.x + bias[e0], v.y + bias[e0+1],
                                   v.z + bias[e0+2], v.w + bias[e0+3]);
            *(float4*)&outF[(size_t)m * DD + e0] = o;
        } else if (MODE == 1) {
            int e0 = bn + c0;
            int h = e0 >> 6, dk0 = e0 & 63;
            int bb = m >> 11, s = m & (SS - 1);
            __half2 h0 = __floats2half2_rn(v.x + bias[e0],   v.y + bias[e0+1]);
            __half2 h1 = __floats2half2_rn(v.z + bias[e0+2], v.w + bias[e0+3]);
            __half2* dst = (__half2*)&outH[(((size_t)(bb * HH + h)) * SS + s) * DK + dk0];
            dst[0] = h0; dst[1] = h1;
        } else if (MODE == 2) {
            int e0 = bn + c0;
            int bb = m >> 11, s = m & (SS - 1);
            float vv[4] = {v.x, v.y, v.z, v.w};
#pragma unroll
            for (int j = 0; j < 4; j++) {
                int e = e0 + j;
                int h = e >> 6, dk = e & 63;
                outH[((size_t)(bb * HH + h) * DK + dk) * SS + s] = __float2half_rn(vv[j] + bias[e]);
            }
        } else if (MODE == 6) {
            int col0 = bn + c0;
            int bb = z >> 4;
            size_t grow = (size_t)z * SS + m;
            float mr = gm[grow], ir = ginv[grow];
            int4 mm = *(const int4*)&mask[((size_t)bb * SS + m) * SS + col0];
            float x0 = mm.x ? v.x * 0.125f : NEGV;
            float x1 = mm.y ? v.y * 0.125f : NEGV;
            float x2 = mm.z ? v.z * 0.125f : NEGV;
            float x3 = mm.w ? v.w * 0.125f : NEGV;
            float p0 = __expf(x0 - mr) * ir;
            float p1 = __expf(x1 - mr) * ir;
            float p2 = __expf(x2 - mr) * ir;
            float p3 = __expf(x3 - mr) * ir;
            *(float4*)&outF[(size_t)z * SS * SS + (size_t)m * SS + col0] =
                make_float4(p0, p1, p2, p3);
            __half2* hdst = (__half2*)&outH[(size_t)z * SS * SS + (size_t)m * SS + col0];
            hdst[0] = __floats2half2_rn(p0, p1);
            hdst[1] = __floats2half2_rn(p2, p3);
        } else { // MODE 4: ctx half (b,s,d)
            int bb = z >> 4, h = z & 15;
            __half2 h0 = __floats2half2_rn(v.x, v.y);
            __half2 h1 = __floats2half2_rn(v.z, v.w);
            __half2* dst = (__half2*)&outH[((size_t)bb * SS + m) * DD + h * DK + bn + c0];
            dst[0] = h0; dst[1] = h1;
        }
    }
}

// ======================= combine per-row tile stats =======================
__global__ __launch_bounds__(256) void k_comb(const float* __restrict__ tmax,
                                              const float* __restrict__ tsum,
                                              float* __restrict__ gm,
                                              float* __restrict__ ginv)
{
    int row = blockIdx.x * 256 + threadIdx.x;
    const float* mx = tmax + (size_t)row * NTILES;
    const float* sx = tsum + (size_t)row * NTILES;
    float m = mx[0];
#pragma unroll
    for (int i = 1; i < NTILES; i++) m = fmaxf(m, mx[i]);
    float S = 0.f;
#pragma unroll
    for (int i = 0; i < NTILES; i++) S += sx[i] * __expf(mx[i] - m);
    gm[row] = m;
    ginv[row] = 1.0f / S;
}

// ======================= fp32 -> fp16 convert =======================
__global__ __launch_bounds__(256) void k_f2h(const float* __restrict__ x,
                                             __half* __restrict__ y)
{
    size_t i = ((size_t)blockIdx.x * 256 + threadIdx.x) * 4;
    float4 v = *(const float4*)(x + i);
    *(__half2*)(y + i)     = __floats2half2_rn(v.x, v.y);
    *(__half2*)(y + i + 2) = __floats2half2_rn(v.z, v.w);
}

// ======================= launch =======================
extern "C" void kernel_launch(void* const* d_in, const int* in_sizes, int n_in,
                              void* d_out, int out_size)
{
    const float* q    = (const float*)d_in[0];
    const float* k    = (const float*)d_in[1];
    const float* v    = (const float*)d_in[2];
    const int*   mask = (const int*)  d_in[3];
    const float* Wq   = (const float*)d_in[4];
    const float* bq_  = (const float*)d_in[5];
    const float* Wk   = (const float*)d_in[6];
    const float* bk_  = (const float*)d_in[7];
    const float* Wv   = (const float*)d_in[8];
    const float* bv_  = (const float*)d_in[9];
    const float* Wo   = (const float*)d_in[10];
    const float* bo_  = (const float*)d_in[11];
    float* out = (float*)d_out;

    const long long out_elems = (long long)MROWS * DD;
    const long long p_elems   = (long long)BB * HH * SS * SS;

    float* p_base;
    if ((long long)out_size >= out_elems + p_elems) {
        p_base = out + out_elems;
    } else {
        void* sp = nullptr;
        cudaGetSymbolAddress(&sp, g_pattn_scratch);
        p_base = (float*)sp;
    }

    void *pa16, *pw16, *pqh, *pkh, *pvt, *pp16, *ptm, *pts, *pgm, *pgi;
    cudaGetSymbolAddress(&pa16, g_a16);
    cudaGetSymbolAddress(&pw16, g_w16);
    cudaGetSymbolAddress(&pqh,  g_qh16);
    cudaGetSymbolAddress(&pkh,  g_kh16);
    cudaGetSymbolAddress(&pvt,  g_vt16);
    cudaGetSymbolAddress(&pp16, g_p16);
    cudaGetSymbolAddress(&ptm,  g_tmax);
    cudaGetSymbolAddress(&pts,  g_tsum);
    cudaGetSymbolAddress(&pgm,  g_gm);
    cudaGetSymbolAddress(&pgi,  g_ginv);
    __half* a16 = (__half*)pa16;
    __half* w16 = (__half*)pw16;
    __half* qh16 = (__half*)pqh;
    __half* kh16 = (__half*)pkh;
    __half* vt16 = (__half*)pvt;
    __half* p16  = (__half*)pp16;
    float* tmax = (float*)ptm;
    float* tsum = (float*)pts;
    float* gmv  = (float*)pgm;
    float* giv  = (float*)pgi;

    const int SM_PROJ = 82048;   // 4*(128+128)*80 + align
    const int SM_STAT = 64128;   // 3*20480 + red 2560 + align
    const int SM_NORM = 65664;   // max(3*20480, esm 64KB) + align
    const int SM_AV   = 61568;   // 4*(128+64)*80 + align
    cudaFuncSetAttribute(tc_mm<2,4,4,4,4,0>, cudaFuncAttributeMaxDynamicSharedMemorySize, SM_PROJ);
    cudaFuncSetAttribute(tc_mm<2,4,4,4,4,1>, cudaFuncAttributeMaxDynamicSharedMemorySize, SM_PROJ);
    cudaFuncSetAttribute(tc_mm<2,4,4,4,4,2>, cudaFuncAttributeMaxDynamicSharedMemorySize, SM_PROJ);
    cudaFuncSetAttribute(tc_mm<2,4,4,4,3,5>, cudaFuncAttributeMaxDynamicSharedMemorySize, SM_STAT);
    cudaFuncSetAttribute(tc_mm<2,4,4,4,3,6>, cudaFuncAttributeMaxDynamicSharedMemorySize, SM_NORM);
    cudaFuncSetAttribute(tc_mm<4,2,2,4,4,4>, cudaFuncAttributeMaxDynamicSharedMemorySize, SM_AV);

    const int nIn = MROWS * DD / 1024;
    const int nW  = DD * DD / 1024;

    dim3 gProj(DD / 128, MROWS / 128, 1);       // (8,32)
    k_f2h<<<nIn, 256>>>(q, a16);
    k_f2h<<<nW, 256>>>(Wq, w16);
    tc_mm<2,4,4,4,4,1><<<gProj, 256, SM_PROJ>>>(a16, DD, 0, w16, DD, 0, DD,
        bq_, nullptr, nullptr, nullptr, nullptr, nullptr, nullptr, qh16);
    k_f2h<<<nIn, 256>>>(k, a16);
    k_f2h<<<nW, 256>>>(Wk, w16);
    tc_mm<2,4,4,4,4,1><<<gProj, 256, SM_PROJ>>>(a16, DD, 0, w16, DD, 0, DD,
        bk_, nullptr, nullptr, nullptr, nullptr, nullptr, nullptr, kh16);
    k_f2h<<<nIn, 256>>>(v, a16);
    k_f2h<<<nW, 256>>>(Wv, w16);
    tc_mm<2,4,4,4,4,2><<<gProj, 256, SM_PROJ>>>(a16, DD, 0, w16, DD, 0, DD,
        bv_, nullptr, nullptr, nullptr, nullptr, nullptr, nullptr, vt16);

    dim3 gScores(SS / 128, SS / 128, BB * HH);  // (16,16,32)
    // pass 1: stats only
    tc_mm<2,4,4,4,3,5><<<gScores, 256, SM_STAT>>>(qh16, DK, (size_t)SS * DK,
        kh16, DK, (size_t)SS * DK, DK,
        nullptr, mask, nullptr, nullptr, tmax, tsum, nullptr, nullptr);
    // combine stats
    k_comb<<<NROWS_TOT / 256, 256>>>(tmax, tsum, gmv, giv);
    // pass 2: recompute + normalized write (fp32 + fp16)
    tc_mm<2,4,4,4,3,6><<<gScores, 256, SM_NORM>>>(qh16, DK, (size_t)SS * DK,
        kh16, DK, (size_t)SS * DK, DK,
        nullptr, mask, gmv, giv, nullptr, nullptr, p_base, p16);

    // AV: ctx = P16 @ Vt^T
    dim3 gAV(1, SS / 128, BB * HH);             // (1,16,32)
    tc_mm<4,2,2,4,4,4><<<gAV, 256, SM_AV>>>(p16, SS, (size_t)SS * SS,
        vt16, SS, (size_t)DK * SS, SS,
        nullptr, nullptr, nullptr, nullptr, nullptr, nullptr, nullptr, a16);

    // output projection
    k_f2h<<<nW, 256>>>(Wo, w16);
    tc_mm<2,4,4,4,4,0><<<gProj, 256, SM_PROJ>>>(a16, DD, 0, w16, DD, 0, DD,
        bo_, nullptr, nullptr, nullptr, nullptr, nullptr, out, nullptr);
}

// round 10
// speedup vs baseline: 1.2447x; 1.0579x over previous
#include <cuda_runtime.h>
#include <cuda_fp16.h>
#include <cstdint>

#define BB 2
#define SS 2048
#define DD 1024
#define HH 16
#define DK 64
#define MROWS (BB*SS)
#define NEGV -1000000000.0f

// ---------------- scratch ----------------
__device__ __align__(128) __half g_a16[(size_t)MROWS*DD];
__device__ __align__(128) __half g_w16[(size_t)DD*DD];
__device__ __align__(128) __half g_qh16[(size_t)BB*HH*SS*DK];
__device__ __align__(128) __half g_kh16[(size_t)BB*HH*SS*DK];
__device__ __align__(128) __half g_vt16[(size_t)BB*HH*DK*SS];
__device__ __align__(128) __half g_p16[(size_t)BB*HH*SS*SS];
__device__ float g_pattn_scratch[(size_t)BB*HH*SS*SS];   // fallback

// ---------------- helpers ----------------
__device__ __forceinline__ uint32_t smem_u32(const void* p) {
    uint32_t a;
    asm("{ .reg .u64 t; cvta.to.shared.u64 t, %1; cvt.u32.u64 %0, t; }" : "=r"(a) : "l"(p));
    return a;
}

#define CP_ASYNC16(dst, src) \
    asm volatile("cp.async.cg.shared.global [%0], [%1], 16;" :: "r"(dst), "l"(src) : "memory")
#define CP_COMMIT() asm volatile("cp.async.commit_group;" ::: "memory")
#define CP_WAIT(n)  asm volatile("cp.async.wait_group %0;" :: "n"(n) : "memory")

__device__ __forceinline__ void ldm_x4(uint32_t addr, uint32_t& r0, uint32_t& r1,
                                       uint32_t& r2, uint32_t& r3) {
    asm volatile("ldmatrix.sync.aligned.m8n8.x4.shared.b16 {%0,%1,%2,%3}, [%4];"
                 : "=r"(r0), "=r"(r1), "=r"(r2), "=r"(r3) : "r"(addr));
}

__device__ __forceinline__ void mma16816(float* c, const uint32_t* a, const uint32_t* b) {
    asm volatile("mma.sync.aligned.m16n8k16.row.col.f32.f16.f16.f32 "
                 "{%0,%1,%2,%3},{%4,%5,%6,%7},{%8,%9},{%0,%1,%2,%3};"
                 : "+f"(c[0]), "+f"(c[1]), "+f"(c[2]), "+f"(c[3])
                 : "r"(a[0]), "r"(a[1]), "r"(a[2]), "r"(a[3]), "r"(b[0]), "r"(b[1]));
}

// (rows x 32 half) tile, 80B padded rows, 256 threads
__device__ __forceinline__ void ld_tile(uint32_t dst, const __half* g, int ldh,
                                        int rows, int tid) {
    for (int ci = tid; ci < rows * 4; ci += 256) {
        int r = ci >> 2, c = ci & 3;
        CP_ASYNC16(dst + (uint32_t)(r * 80 + c * 16), g + (size_t)r * ldh + c * 8);
    }
}

// ============================================================================
// fp16 MMA GEMM, 256 threads / 8 warps, 2 CTAs per SM.
// MODE: 0 proj->fp32 flat +bias | 1 proj->half (z,s,dk) +bias
//       2 proj->half (z,dk,s) +bias | 3 scores masked fp32 | 4 AV ctx half
// ============================================================================
template<int WARPS_M, int WARPS_N, int WMI, int WNI, int S, int MODE>
__global__ __launch_bounds__(256, 2) void tc_mm(
    const __half* __restrict__ A, int lda, size_t aZ,
    const __half* __restrict__ B, int ldb, size_t bZ,
    int K,
    const float* __restrict__ bias,
    const int*   __restrict__ mask,
    float* __restrict__ outF,
    __half* __restrict__ outH)
{
    constexpr int BM  = WARPS_M * WMI * 16;
    constexpr int BN  = WARPS_N * WNI * 8;
    constexpr int ASZ = BM * 80;
    constexpr int BSZ = BN * 80;
    constexpr int STG = ASZ + BSZ;
    constexpr int NJ  = WNI / 2;

    extern __shared__ char smraw[];
    char* sm = (char*)(((uintptr_t)smraw + 127) & ~(uintptr_t)127);
    uint32_t smu = smem_u32(sm);

    const int tid  = threadIdx.x;
    const int w    = tid >> 5, lane = tid & 31;
    const int bn   = blockIdx.x * BN, bm = blockIdx.y * BM;
    const int z    = blockIdx.z;

    A += (size_t)z * aZ + (size_t)bm * lda;
    B += (size_t)z * bZ + (size_t)bn * ldb;

    const int wm = (w / WARPS_N) * (WMI * 16);
    const int wn = (w % WARPS_N) * (WNI * 8);

    float acc[WMI][WNI][4];
#pragma unroll
    for (int mi = 0; mi < WMI; mi++)
#pragma unroll
        for (int nt = 0; nt < WNI; nt++)
#pragma unroll
            for (int x = 0; x < 4; x++) acc[mi][nt][x] = 0.f;

    const int NK = K / 32;
#pragma unroll
    for (int s = 0; s < S - 1; s++) {
        if (s < NK) {
            ld_tile(smu + s * STG,       A + s * 32, lda, BM, tid);
            ld_tile(smu + s * STG + ASZ, B + s * 32, ldb, BN, tid);
        }
        CP_COMMIT();
    }

    const int rA = (lane & 7) + ((lane >> 3) & 1) * 8;
    const int kO = ((lane >> 4) << 3) * 2;

    for (int kt = 0; kt < NK; kt++) {
        CP_WAIT(S - 2);
        __syncthreads();
        uint32_t sA = smu + (kt % S) * STG;
        uint32_t sB = sA + ASZ;
#pragma unroll
        for (int ks = 0; ks < 2; ks++) {
            uint32_t a[WMI][4], bf[WNI][2];
            uint32_t kb = (uint32_t)(ks * 32 + kO);
#pragma unroll
            for (int mi = 0; mi < WMI; mi++)
                ldm_x4(sA + (uint32_t)((wm + mi * 16 + rA) * 80) + kb,
                       a[mi][0], a[mi][1], a[mi][2], a[mi][3]);
#pragma unroll
            for (int nj = 0; nj < NJ; nj++) {
                uint32_t r0, r1, r2, r3;
                ldm_x4(sB + (uint32_t)((wn + nj * 16 + rA) * 80) + kb, r0, r1, r2, r3);
                bf[nj * 2 + 0][0] = r0; bf[nj * 2 + 1][0] = r1;
                bf[nj * 2 + 0][1] = r2; bf[nj * 2 + 1][1] = r3;
            }
#pragma unroll
            for (int mi = 0; mi < WMI; mi++)
#pragma unroll
                for (int nt = 0; nt < WNI; nt++)
                    mma16816(acc[mi][nt], a[mi], bf[nt]);
        }
        int ns = kt + S - 1;
        if (ns < NK) {
            ld_tile(smu + (ns % S) * STG,       A + ns * 32, lda, BM, tid);
            ld_tile(smu + (ns % S) * STG + ASZ, B + ns * 32, ldb, BN, tid);
        }
        CP_COMMIT();
    }
    CP_WAIT(0);
    __syncthreads();

    // ---- stage accumulators through smem for coalesced writes ----
    float* esm = (float*)sm;
    const int er = lane >> 2, ec = (lane & 3) * 2;
#pragma unroll
    for (int mi = 0; mi < WMI; mi++)
#pragma unroll
        for (int nt = 0; nt < WNI; nt++) {
            int r0 = wm + mi * 16 + er;
            int c0 = wn + nt * 8 + ec;
            *(float2*)&esm[(size_t)r0 * BN + c0]       = make_float2(acc[mi][nt][0], acc[mi][nt][1]);
            *(float2*)&esm[(size_t)(r0 + 8) * BN + c0] = make_float2(acc[mi][nt][2], acc[mi][nt][3]);
        }
    __syncthreads();

    for (int ci = tid; ci < BM * BN / 4; ci += 256) {
        int r  = ci / (BN / 4);
        int c0 = (ci % (BN / 4)) * 4;
        float4 v = *(const float4*)&esm[(size_t)r * BN + c0];
        int m = bm + r;
        if (MODE == 0) {
            int e0 = bn + c0;
            float4 o = make_float4(v.x + bias[e0], v.y + bias[e0+1],
                                   v.z + bias[e0+2], v.w + bias[e0+3]);
            *(float4*)&outF[(size_t)m * DD + e0] = o;
        } else if (MODE == 1) {
            int e0 = bn + c0;
            int h = e0 >> 6, dk0 = e0 & 63;
            int bb = m >> 11, s = m & (SS - 1);
            __half2 h0 = __floats2half2_rn(v.x + bias[e0],   v.y + bias[e0+1]);
            __half2 h1 = __floats2half2_rn(v.z + bias[e0+2], v.w + bias[e0+3]);
            __half2* dst = (__half2*)&outH[(((size_t)(bb * HH + h)) * SS + s) * DK + dk0];
            dst[0] = h0; dst[1] = h1;
        } else if (MODE == 2) {
            int e0 = bn + c0;
            int bb = m >> 11, s = m & (SS - 1);
            float vv[4] = {v.x, v.y, v.z, v.w};
#pragma unroll
            for (int j = 0; j < 4; j++) {
                int e = e0 + j;
                int h = e >> 6, dk = e & 63;
                outH[((size_t)(bb * HH + h) * DK + dk) * SS + s] = __float2half_rn(vv[j] + bias[e]);
            }
        } else if (MODE == 3) {
            int col0 = bn + c0;
            int bb = z >> 4;
            int4 mm = *(const int4*)&mask[((size_t)bb * SS + m) * SS + col0];
            float4 o;
            o.x = mm.x ? v.x * 0.125f : NEGV;
            o.y = mm.y ? v.y * 0.125f : NEGV;
            o.z = mm.z ? v.z * 0.125f : NEGV;
            o.w = mm.w ? v.w * 0.125f : NEGV;
            *(float4*)&outF[(size_t)z * SS * SS + (size_t)m * SS + col0] = o;
        } else { // MODE 4: ctx half (b,s,d); m = local q-row, z = b*HH+h
            int bb = z >> 4, h = z & 15;
            __half2 h0 = __floats2half2_rn(v.x, v.y);
            __half2 h1 = __floats2half2_rn(v.z, v.w);
            __half2* dst = (__half2*)&outH[((size_t)bb * SS + m) * DD + h * DK + bn + c0];
            dst[0] = h0; dst[1] = h1;
        }
    }
}

// ======================= fp32 -> fp16 convert =======================
__global__ __launch_bounds__(256) void k_f2h(const float* __restrict__ x,
                                             __half* __restrict__ y)
{
    size_t i = ((size_t)blockIdx.x * 256 + threadIdx.x) * 4;
    float4 v = *(const float4*)(x + i);
    *(__half2*)(y + i)     = __floats2half2_rn(v.x, v.y);
    *(__half2*)(y + i + 2) = __floats2half2_rn(v.z, v.w);
}

// ======================= softmax: fp32 in-place + fp16 copy =======================
__global__ __launch_bounds__(256) void k_softmax(float* __restrict__ P,
                                                 __half* __restrict__ P16)
{
    __shared__ float red[8];
    const size_t row = blockIdx.x;
    float* p = P + row * SS;
    __half* p16 = P16 + row * SS;
    const int tid = threadIdx.x;

    float4 v0 = ((const float4*)p)[tid];
    float4 v1 = ((const float4*)p)[tid + 256];

    float m = fmaxf(fmaxf(fmaxf(v0.x, v0.y), fmaxf(v0.z, v0.w)),
                    fmaxf(fmaxf(v1.x, v1.y), fmaxf(v1.z, v1.w)));
#pragma unroll
    for (int o = 16; o; o >>= 1) m = fmaxf(m, __shfl_xor_sync(~0u, m, o));
    if ((tid & 31) == 0) red[tid >> 5] = m;
    __syncthreads();
    m = red[0];
#pragma unroll
    for (int i = 1; i < 8; i++) m = fmaxf(m, red[i]);
    __syncthreads();

    float4 e0, e1;
    e0.x = __expf(v0.x - m); e0.y = __expf(v0.y - m);
    e0.z = __expf(v0.z - m); e0.w = __expf(v0.w - m);
    e1.x = __expf(v1.x - m); e1.y = __expf(v1.y - m);
    e1.z = __expf(v1.z - m); e1.w = __expf(v1.w - m);
    float s = (e0.x + e0.y) + (e0.z + e0.w) + (e1.x + e1.y) + (e1.z + e1.w);
#pragma unroll
    for (int o = 16; o; o >>= 1) s += __shfl_xor_sync(~0u, s, o);
    if ((tid & 31) == 0) red[tid >> 5] = s;
    __syncthreads();
    s = red[0];
#pragma unroll
    for (int i = 1; i < 8; i++) s += red[i];
    float inv = 1.0f / s;

    e0.x *= inv; e0.y *= inv; e0.z *= inv; e0.w *= inv;
    e1.x *= inv; e1.y *= inv; e1.z *= inv; e1.w *= inv;
    ((float4*)p)[tid]       = e0;
    ((float4*)p)[tid + 256] = e1;
    __half2* ph = (__half2*)p16;
    ph[tid * 2 + 0]   = __floats2half2_rn(e0.x, e0.y);
    ph[tid * 2 + 1]   = __floats2half2_rn(e0.z, e0.w);
    ph[512 + tid * 2] = __floats2half2_rn(e1.x, e1.y);
    ph[513 + tid * 2] = __floats2half2_rn(e1.z, e1.w);
}

// ======================= launch =======================
extern "C" void kernel_launch(void* const* d_in, const int* in_sizes, int n_in,
                              void* d_out, int out_size)
{
    const float* q    = (const float*)d_in[0];
    const float* k    = (const float*)d_in[1];
    const float* v    = (const float*)d_in[2];
    const int*   mask = (const int*)  d_in[3];
    const float* Wq   = (const float*)d_in[4];
    const float* bq_  = (const float*)d_in[5];
    const float* Wk   = (const float*)d_in[6];
    const float* bk_  = (const float*)d_in[7];
    const float* Wv   = (const float*)d_in[8];
    const float* bv_  = (const float*)d_in[9];
    const float* Wo   = (const float*)d_in[10];
    const float* bo_  = (const float*)d_in[11];
    float* out = (float*)d_out;

    const long long out_elems = (long long)MROWS * DD;
    const long long p_elems   = (long long)BB * HH * SS * SS;

    float* p_base;
    if ((long long)out_size >= out_elems + p_elems) {
        p_base = out + out_elems;
    } else {
        void* sp = nullptr;
        cudaGetSymbolAddress(&sp, g_pattn_scratch);
        p_base = (float*)sp;
    }

    void *pa16, *pw16, *pqh, *pkh, *pvt, *pp16;
    cudaGetSymbolAddress(&pa16, g_a16);
    cudaGetSymbolAddress(&pw16, g_w16);
    cudaGetSymbolAddress(&pqh,  g_qh16);
    cudaGetSymbolAddress(&pkh,  g_kh16);
    cudaGetSymbolAddress(&pvt,  g_vt16);
    cudaGetSymbolAddress(&pp16, g_p16);
    __half* a16 = (__half*)pa16;
    __half* w16 = (__half*)pw16;
    __half* qh16 = (__half*)pqh;
    __half* kh16 = (__half*)pkh;
    __half* vt16 = (__half*)pvt;
    __half* p16  = (__half*)pp16;

    const int SM_PROJ = 82048;   // 4*(128+128)*80 + align  (esm 64KB fits)
    const int SM_SC   = 65664;   // max(3*20480, esm 64KB) + align
    const int SM_AV   = 61568;   // 4*(128+64)*80 + align
    cudaFuncSetAttribute(tc_mm<2,4,4,4,4,0>, cudaFuncAttributeMaxDynamicSharedMemorySize, SM_PROJ);
    cudaFuncSetAttribute(tc_mm<2,4,4,4,4,1>, cudaFuncAttributeMaxDynamicSharedMemorySize, SM_PROJ);
    cudaFuncSetAttribute(tc_mm<2,4,4,4,4,2>, cudaFuncAttributeMaxDynamicSharedMemorySize, SM_PROJ);
    cudaFuncSetAttribute(tc_mm<2,4,4,4,3,3>, cudaFuncAttributeMaxDynamicSharedMemorySize, SM_SC);
    cudaFuncSetAttribute(tc_mm<4,2,2,4,4,4>, cudaFuncAttributeMaxDynamicSharedMemorySize, SM_AV);

    const int nIn = MROWS * DD / 1024;
    const int nW  = DD * DD / 1024;

    dim3 gProj(DD / 128, MROWS / 128, 1);       // (8,32)
    k_f2h<<<nIn, 256>>>(q, a16);
    k_f2h<<<nW, 256>>>(Wq, w16);
    tc_mm<2,4,4,4,4,1><<<gProj, 256, SM_PROJ>>>(a16, DD, 0, w16, DD, 0, DD,
        bq_, nullptr, nullptr, qh16);
    k_f2h<<<nIn, 256>>>(k, a16);
    k_f2h<<<nW, 256>>>(Wk, w16);
    tc_mm<2,4,4,4,4,1><<<gProj, 256, SM_PROJ>>>(a16, DD, 0, w16, DD, 0, DD,
        bk_, nullptr, nullptr, kh16);
    k_f2h<<<nIn, 256>>>(v, a16);
    k_f2h<<<nW, 256>>>(Wv, w16);
    tc_mm<2,4,4,4,4,2><<<gProj, 256, SM_PROJ>>>(a16, DD, 0, w16, DD, 0, DD,
        bv_, nullptr, nullptr, vt16);

    // scores (raw masked scaled) -> fp32 P
    dim3 gScores(SS / 128, SS / 128, BB * HH);  // (16,16,32)
    tc_mm<2,4,4,4,3,3><<<gScores, 256, SM_SC>>>(qh16, DK, (size_t)SS * DK,
        kh16, DK, (size_t)SS * DK, DK,
        nullptr, mask, p_base, nullptr);

    // softmax in-place + fp16 copy
    k_softmax<<<BB * HH * SS, 256>>>(p_base, p16);

    // AV: ctx = P16 @ Vt^T
    dim3 gAV(1, SS / 128, BB * HH);             // (1,16,32)
    tc_mm<4,2,2,4,4,4><<<gAV, 256, SM_AV>>>(p16, SS, (size_t)SS * SS,
        vt16, SS, (size_t)DK * SS, SS,
        nullptr, nullptr, nullptr, a16);

    // output projection
    k_f2h<<<nW, 256>>>(Wo, w16);
    tc_mm<2,4,4,4,4,0><<<gProj, 256, SM_PROJ>>>(a16, DD, 0, w16, DD, 0, DD,
        bo_, nullptr, out, nullptr);
}

// round 11
// speedup vs baseline: 1.3154x; 1.0568x over previous
#include <cuda_runtime.h>
#include <cuda_fp16.h>
#include <cstdint>

#define BB 2
#define SS 2048
#define DD 1024
#define HH 16
#define DK 64
#define MROWS (BB*SS)
#define NEGV -1000000000.0f

// ---------------- scratch ----------------
__device__ __align__(128) __half g_in16[(size_t)3*MROWS*DD];   // q,k,v fp16
__device__ __align__(128) __half g_a16[(size_t)MROWS*DD];      // ctx fp16
__device__ __align__(128) __half g_w16[(size_t)4*DD*DD];       // Wq,Wk,Wv,Wo fp16
__device__ __align__(128) __half g_qh16[(size_t)BB*HH*SS*DK];
__device__ __align__(128) __half g_kh16[(size_t)BB*HH*SS*DK];
__device__ __align__(128) __half g_vt16[(size_t)BB*HH*DK*SS];
__device__ __align__(128) __half g_p16[(size_t)BB*HH*SS*SS];
__device__ float g_pattn_scratch[(size_t)BB*HH*SS*SS];         // fallback

// ---------------- helpers ----------------
__device__ __forceinline__ uint32_t smem_u32(const void* p) {
    uint32_t a;
    asm("{ .reg .u64 t; cvta.to.shared.u64 t, %1; cvt.u32.u64 %0, t; }" : "=r"(a) : "l"(p));
    return a;
}

#define CP_ASYNC16(dst, src) \
    asm volatile("cp.async.cg.shared.global [%0], [%1], 16;" :: "r"(dst), "l"(src) : "memory")
#define CP_COMMIT() asm volatile("cp.async.commit_group;" ::: "memory")
#define CP_WAIT(n)  asm volatile("cp.async.wait_group %0;" :: "n"(n) : "memory")

__device__ __forceinline__ void ldm_x4(uint32_t addr, uint32_t& r0, uint32_t& r1,
                                       uint32_t& r2, uint32_t& r3) {
    asm volatile("ldmatrix.sync.aligned.m8n8.x4.shared.b16 {%0,%1,%2,%3}, [%4];"
                 : "=r"(r0), "=r"(r1), "=r"(r2), "=r"(r3) : "r"(addr));
}

__device__ __forceinline__ void mma16816(float* c, const uint32_t* a, const uint32_t* b) {
    asm volatile("mma.sync.aligned.m16n8k16.row.col.f32.f16.f16.f32 "
                 "{%0,%1,%2,%3},{%4,%5,%6,%7},{%8,%9},{%0,%1,%2,%3};"
                 : "+f"(c[0]), "+f"(c[1]), "+f"(c[2]), "+f"(c[3])
                 : "r"(a[0]), "r"(a[1]), "r"(a[2]), "r"(a[3]), "r"(b[0]), "r"(b[1]));
}

// (rows x 32 half) tile, 80B padded rows, 256 threads
__device__ __forceinline__ void ld_tile(uint32_t dst, const __half* g, int ldh,
                                        int rows, int tid) {
    for (int ci = tid; ci < rows * 4; ci += 256) {
        int r = ci >> 2, c = ci & 3;
        CP_ASYNC16(dst + (uint32_t)(r * 80 + c * 16), g + (size_t)r * ldh + c * 8);
    }
}

// ============================================================================
// fp16 MMA GEMM, 256 threads / 8 warps, 2 CTAs per SM.
// MODE: 0 proj->fp32 flat +bias | 1 proj->half (z,s,dk) +bias
//       2 proj->half (z,dk,s) +bias (coalesced transpose) | 3 scores masked fp32
//       4 AV ctx half
// ============================================================================
template<int WARPS_M, int WARPS_N, int WMI, int WNI, int S, int MODE>
__global__ __launch_bounds__(256, 2) void tc_mm(
    const __half* __restrict__ A, int lda, size_t aZ,
    const __half* __restrict__ B, int ldb, size_t bZ,
    int K,
    const float* __restrict__ bias,
    const int*   __restrict__ mask,
    float* __restrict__ outF,
    __half* __restrict__ outH)
{
    constexpr int BM  = WARPS_M * WMI * 16;
    constexpr int BN  = WARPS_N * WNI * 8;
    constexpr int BNP = (MODE == 2) ? BN + 5 : BN;   // odd pad for transpose reads
    constexpr int ASZ = BM * 80;
    constexpr int BSZ = BN * 80;
    constexpr int STG = ASZ + BSZ;
    constexpr int NJ  = WNI / 2;

    extern __shared__ char smraw[];
    char* sm = (char*)(((uintptr_t)smraw + 127) & ~(uintptr_t)127);
    uint32_t smu = smem_u32(sm);

    const int tid  = threadIdx.x;
    const int w    = tid >> 5, lane = tid & 31;
    const int bn   = blockIdx.x * BN, bm = blockIdx.y * BM;
    const int z    = blockIdx.z;

    A += (size_t)z * aZ + (size_t)bm * lda;
    B += (size_t)z * bZ + (size_t)bn * ldb;

    const int wm = (w / WARPS_N) * (WMI * 16);
    const int wn = (w % WARPS_N) * (WNI * 8);

    float acc[WMI][WNI][4];
#pragma unroll
    for (int mi = 0; mi < WMI; mi++)
#pragma unroll
        for (int nt = 0; nt < WNI; nt++)
#pragma unroll
            for (int x = 0; x < 4; x++) acc[mi][nt][x] = 0.f;

    const int NK = K / 32;
#pragma unroll
    for (int s = 0; s < S - 1; s++) {
        if (s < NK) {
            ld_tile(smu + s * STG,       A + s * 32, lda, BM, tid);
            ld_tile(smu + s * STG + ASZ, B + s * 32, ldb, BN, tid);
        }
        CP_COMMIT();
    }

    const int rA = (lane & 7) + ((lane >> 3) & 1) * 8;
    const int kO = ((lane >> 4) << 3) * 2;

    for (int kt = 0; kt < NK; kt++) {
        CP_WAIT(S - 2);
        __syncthreads();
        uint32_t sA = smu + (kt % S) * STG;
        uint32_t sB = sA + ASZ;
#pragma unroll
        for (int ks = 0; ks < 2; ks++) {
            uint32_t a[WMI][4], bf[WNI][2];
            uint32_t kb = (uint32_t)(ks * 32 + kO);
#pragma unroll
            for (int mi = 0; mi < WMI; mi++)
                ldm_x4(sA + (uint32_t)((wm + mi * 16 + rA) * 80) + kb,
                       a[mi][0], a[mi][1], a[mi][2], a[mi][3]);
#pragma unroll
            for (int nj = 0; nj < NJ; nj++) {
                uint32_t r0, r1, r2, r3;
                ldm_x4(sB + (uint32_t)((wn + nj * 16 + rA) * 80) + kb, r0, r1, r2, r3);
                bf[nj * 2 + 0][0] = r0; bf[nj * 2 + 1][0] = r1;
                bf[nj * 2 + 0][1] = r2; bf[nj * 2 + 1][1] = r3;
            }
#pragma unroll
            for (int mi = 0; mi < WMI; mi++)
#pragma unroll
                for (int nt = 0; nt < WNI; nt++)
                    mma16816(acc[mi][nt], a[mi], bf[nt]);
        }
        int ns = kt + S - 1;
        if (ns < NK) {
            ld_tile(smu + (ns % S) * STG,       A + ns * 32, lda, BM, tid);
            ld_tile(smu + (ns % S) * STG + ASZ, B + ns * 32, ldb, BN, tid);
        }
        CP_COMMIT();
    }
    CP_WAIT(0);
    __syncthreads();

    // ---- stage accumulators through smem for coalesced writes ----
    float* esm = (float*)sm;
    const int er = lane >> 2, ec = (lane & 3) * 2;
#pragma unroll
    for (int mi = 0; mi < WMI; mi++)
#pragma unroll
        for (int nt = 0; nt < WNI; nt++) {
            int r0 = wm + mi * 16 + er;
            int c0 = wn + nt * 8 + ec;
            if (MODE == 2) {  // padded stride, scalar stores (alignment)
                esm[(size_t)r0 * BNP + c0]           = acc[mi][nt][0];
                esm[(size_t)r0 * BNP + c0 + 1]       = acc[mi][nt][1];
                esm[(size_t)(r0 + 8) * BNP + c0]     = acc[mi][nt][2];
                esm[(size_t)(r0 + 8) * BNP + c0 + 1] = acc[mi][nt][3];
            } else {
                *(float2*)&esm[(size_t)r0 * BN + c0]       = make_float2(acc[mi][nt][0], acc[mi][nt][1]);
                *(float2*)&esm[(size_t)(r0 + 8) * BN + c0] = make_float2(acc[mi][nt][2], acc[mi][nt][3]);
            }
        }
    __syncthreads();

    if (MODE == 2) {
        // transpose readout: each thread handles one e-column, 4 consecutive m
        const int bb = bm >> 11;
        const int sbase = bm & (SS - 1);
        for (int ci = tid; ci < BN * (BM / 4); ci += 256) {
            int e  = ci >> 5;          // BM/4 == 32
            int mg = ci & 31;
            int eg = bn + e;
            int h = eg >> 6, dk = eg & 63;
            float bv = bias[eg];
            float v0 = esm[(size_t)(mg * 4 + 0) * BNP + e] + bv;
            float v1 = esm[(size_t)(mg * 4 + 1) * BNP + e] + bv;
            float v2 = esm[(size_t)(mg * 4 + 2) * BNP + e] + bv;
            float v3 = esm[(size_t)(mg * 4 + 3) * BNP + e] + bv;
            __half2* dst = (__half2*)&outH[((size_t)((bb * HH + h)) * DK + dk) * SS
                                           + sbase + mg * 4];
            dst[0] = __floats2half2_rn(v0, v1);
            dst[1] = __floats2half2_rn(v2, v3);
        }
        return;
    }

    for (int ci = tid; ci < BM * BN / 4; ci += 256) {
        int r  = ci / (BN / 4);
        int c0 = (ci % (BN / 4)) * 4;
        float4 v = *(const float4*)&esm[(size_t)r * BN + c0];
        int m = bm + r;
        if (MODE == 0) {
            int e0 = bn + c0;
            float4 o = make_float4(v.x + bias[e0], v.y + bias[e0+1],
                                   v.z + bias[e0+2], v.w + bias[e0+3]);
            *(float4*)&outF[(size_t)m * DD + e0] = o;
        } else if (MODE == 1) {
            int e0 = bn + c0;
            int h = e0 >> 6, dk0 = e0 & 63;
            int bb = m >> 11, s = m & (SS - 1);
            __half2 h0 = __floats2half2_rn(v.x + bias[e0],   v.y + bias[e0+1]);
            __half2 h1 = __floats2half2_rn(v.z + bias[e0+2], v.w + bias[e0+3]);
            __half2* dst = (__half2*)&outH[(((size_t)(bb * HH + h)) * SS + s) * DK + dk0];
            dst[0] = h0; dst[1] = h1;
        } else if (MODE == 3) {
            int col0 = bn + c0;
            int bb = z >> 4;
            int4 mm = *(const int4*)&mask[((size_t)bb * SS + m) * SS + col0];
            float4 o;
            o.x = mm.x ? v.x * 0.125f : NEGV;
            o.y = mm.y ? v.y * 0.125f : NEGV;
            o.z = mm.z ? v.z * 0.125f : NEGV;
            o.w = mm.w ? v.w * 0.125f : NEGV;
            *(float4*)&outF[(size_t)z * SS * SS + (size_t)m * SS + col0] = o;
        } else { // MODE 4: ctx half (b,s,d); m = local q-row, z = b*HH+h
            int bb = z >> 4, h = z & 15;
            __half2 h0 = __floats2half2_rn(v.x, v.y);
            __half2 h1 = __floats2half2_rn(v.z, v.w);
            __half2* dst = (__half2*)&outH[((size_t)bb * SS + m) * DD + h * DK + bn + c0];
            dst[0] = h0; dst[1] = h1;
        }
    }
}

// ======================= batched fp32 -> fp16 converts =======================
__global__ __launch_bounds__(256) void k_f2h3(const float* __restrict__ x0,
                                              const float* __restrict__ x1,
                                              const float* __restrict__ x2,
                                              __half* __restrict__ y)
{
    const float* x = (blockIdx.y == 0) ? x0 : (blockIdx.y == 1) ? x1 : x2;
    __half* yy = y + (size_t)blockIdx.y * MROWS * DD;
    size_t i = ((size_t)blockIdx.x * 256 + threadIdx.x) * 4;
    float4 v = *(const float4*)(x + i);
    *(__half2*)(yy + i)     = __floats2half2_rn(v.x, v.y);
    *(__half2*)(yy + i + 2) = __floats2half2_rn(v.z, v.w);
}

__global__ __launch_bounds__(256) void k_f2h4(const float* __restrict__ x0,
                                              const float* __restrict__ x1,
                                              const float* __restrict__ x2,
                                              const float* __restrict__ x3,
                                              __half* __restrict__ y)
{
    const float* x = (blockIdx.y == 0) ? x0 : (blockIdx.y == 1) ? x1
                   : (blockIdx.y == 2) ? x2 : x3;
    __half* yy = y + (size_t)blockIdx.y * DD * DD;
    size_t i = ((size_t)blockIdx.x * 256 + threadIdx.x) * 4;
    float4 v = *(const float4*)(x + i);
    *(__half2*)(yy + i)     = __floats2half2_rn(v.x, v.y);
    *(__half2*)(yy + i + 2) = __floats2half2_rn(v.z, v.w);
}

// ======================= softmax: fp32 in-place + fp16 copy =======================
__global__ __launch_bounds__(256) void k_softmax(float* __restrict__ P,
                                                 __half* __restrict__ P16)
{
    __shared__ float red[8];
    const size_t row = blockIdx.x;
    float* p = P + row * SS;
    __half* p16 = P16 + row * SS;
    const int tid = threadIdx.x;

    float4 v0 = ((const float4*)p)[tid];
    float4 v1 = ((const float4*)p)[tid + 256];

    float m = fmaxf(fmaxf(fmaxf(v0.x, v0.y), fmaxf(v0.z, v0.w)),
                    fmaxf(fmaxf(v1.x, v1.y), fmaxf(v1.z, v1.w)));
#pragma unroll
    for (int o = 16; o; o >>= 1) m = fmaxf(m, __shfl_xor_sync(~0u, m, o));
    if ((tid & 31) == 0) red[tid >> 5] = m;
    __syncthreads();
    m = red[0];
#pragma unroll
    for (int i = 1; i < 8; i++) m = fmaxf(m, red[i]);
    __syncthreads();

    float4 e0, e1;
    e0.x = __expf(v0.x - m); e0.y = __expf(v0.y - m);
    e0.z = __expf(v0.z - m); e0.w = __expf(v0.w - m);
    e1.x = __expf(v1.x - m); e1.y = __expf(v1.y - m);
    e1.z = __expf(v1.z - m); e1.w = __expf(v1.w - m);
    float s = (e0.x + e0.y) + (e0.z + e0.w) + (e1.x + e1.y) + (e1.z + e1.w);
#pragma unroll
    for (int o = 16; o; o >>= 1) s += __shfl_xor_sync(~0u, s, o);
    if ((tid & 31) == 0) red[tid >> 5] = s;
    __syncthreads();
    s = red[0];
#pragma unroll
    for (int i = 1; i < 8; i++) s += red[i];
    float inv = 1.0f / s;

    e0.x *= inv; e0.y *= inv; e0.z *= inv; e0.w *= inv;
    e1.x *= inv; e1.y *= inv; e1.z *= inv; e1.w *= inv;
    ((float4*)p)[tid]       = e0;
    ((float4*)p)[tid + 256] = e1;
    __half2* ph = (__half2*)p16;
    ph[tid * 2 + 0]   = __floats2half2_rn(e0.x, e0.y);
    ph[tid * 2 + 1]   = __floats2half2_rn(e0.z, e0.w);
    ph[512 + tid * 2] = __floats2half2_rn(e1.x, e1.y);
    ph[513 + tid * 2] = __floats2half2_rn(e1.z, e1.w);
}

// ======================= launch =======================
extern "C" void kernel_launch(void* const* d_in, const int* in_sizes, int n_in,
                              void* d_out, int out_size)
{
    const float* q    = (const float*)d_in[0];
    const float* k    = (const float*)d_in[1];
    const float* v    = (const float*)d_in[2];
    const int*   mask = (const int*)  d_in[3];
    const float* Wq   = (const float*)d_in[4];
    const float* bq_  = (const float*)d_in[5];
    const float* Wk   = (const float*)d_in[6];
    const float* bk_  = (const float*)d_in[7];
    const float* Wv   = (const float*)d_in[8];
    const float* bv_  = (const float*)d_in[9];
    const float* Wo   = (const float*)d_in[10];
    const float* bo_  = (const float*)d_in[11];
    float* out = (float*)d_out;

    const long long out_elems = (long long)MROWS * DD;
    const long long p_elems   = (long long)BB * HH * SS * SS;

    float* p_base;
    if ((long long)out_size >= out_elems + p_elems) {
        p_base = out + out_elems;
    } else {
        void* sp = nullptr;
        cudaGetSymbolAddress(&sp, g_pattn_scratch);
        p_base = (float*)sp;
    }

    void *pin16, *pa16, *pw16, *pqh, *pkh, *pvt, *pp16;
    cudaGetSymbolAddress(&pin16, g_in16);
    cudaGetSymbolAddress(&pa16, g_a16);
    cudaGetSymbolAddress(&pw16, g_w16);
    cudaGetSymbolAddress(&pqh,  g_qh16);
    cudaGetSymbolAddress(&pkh,  g_kh16);
    cudaGetSymbolAddress(&pvt,  g_vt16);
    cudaGetSymbolAddress(&pp16, g_p16);
    __half* in16 = (__half*)pin16;
    __half* a16 = (__half*)pa16;
    __half* w16 = (__half*)pw16;
    __half* qh16 = (__half*)pqh;
    __half* kh16 = (__half*)pkh;
    __half* vt16 = (__half*)pvt;
    __half* p16  = (__half*)pp16;

    const size_t inOff = (size_t)MROWS * DD;
    const size_t wOff  = (size_t)DD * DD;

    const int SM_PROJ = 82048;    // 4*(128+128)*80 + align
    const int SM_PROJ2 = 82048;   // MODE2: esm 128*133*4=68KB < pipeline smem, fits
    const int SM_SC   = 65664;    // max(3*20480, esm 64KB) + align
    const int SM_AV   = 102528;   // 4*(256+64)*80 + align
    cudaFuncSetAttribute(tc_mm<2,4,4,4,4,0>, cudaFuncAttributeMaxDynamicSharedMemorySize, SM_PROJ);
    cudaFuncSetAttribute(tc_mm<2,4,4,4,4,1>, cudaFuncAttributeMaxDynamicSharedMemorySize, SM_PROJ);
    cudaFuncSetAttribute(tc_mm<2,4,4,4,4,2>, cudaFuncAttributeMaxDynamicSharedMemorySize, SM_PROJ2);
    cudaFuncSetAttribute(tc_mm<2,4,4,4,3,3>, cudaFuncAttributeMaxDynamicSharedMemorySize, SM_SC);
    cudaFuncSetAttribute(tc_mm<4,2,4,4,4,4>, cudaFuncAttributeMaxDynamicSharedMemorySize, SM_AV);

    const int nIn = MROWS * DD / 1024;
    const int nW  = DD * DD / 1024;

    // batched converts (2 launches instead of 7)
    k_f2h3<<<dim3(nIn, 3), 256>>>(q, k, v, in16);
    k_f2h4<<<dim3(nW, 4), 256>>>(Wq, Wk, Wv, Wo, w16);

    dim3 gProj(DD / 128, MROWS / 128, 1);       // (8,32)
    tc_mm<2,4,4,4,4,1><<<gProj, 256, SM_PROJ>>>(in16, DD, 0, w16, DD, 0, DD,
        bq_, nullptr, nullptr, qh16);
    tc_mm<2,4,4,4,4,1><<<gProj, 256, SM_PROJ>>>(in16 + inOff, DD, 0, w16 + wOff, DD, 0, DD,
        bk_, nullptr, nullptr, kh16);
    tc_mm<2,4,4,4,4,2><<<gProj, 256, SM_PROJ2>>>(in16 + 2 * inOff, DD, 0, w16 + 2 * wOff, DD, 0, DD,
        bv_, nullptr, nullptr, vt16);

    // scores (raw masked scaled) -> fp32 P
    dim3 gScores(SS / 128, SS / 128, BB * HH);  // (16,16,32)
    tc_mm<2,4,4,4,3,3><<<gScores, 256, SM_SC>>>(qh16, DK, (size_t)SS * DK,
        kh16, DK, (size_t)SS * DK, DK,
        nullptr, mask, p_base, nullptr);

    // softmax in-place + fp16 copy
    k_softmax<<<BB * HH * SS, 256>>>(p_base, p16);

    // AV: ctx = P16 @ Vt^T   (BM=256, BN=64, warp tile 64x32)
    dim3 gAV(1, SS / 256, BB * HH);             // (1,8,32)
    tc_mm<4,2,4,4,4,4><<<gAV, 256, SM_AV>>>(p16, SS, (size_t)SS * SS,
        vt16, SS, (size_t)DK * SS, SS,
        nullptr, nullptr, nullptr, a16);

    // output projection
    tc_mm<2,4,4,4,4,0><<<gProj, 256, SM_PROJ>>>(a16, DD, 0, w16 + 3 * wOff, DD, 0, DD,
        bo_, nullptr, out, nullptr);
}

// round 12
// speedup vs baseline: 1.3190x; 1.0027x over previous
#include <cuda_runtime.h>
#include <cuda_fp16.h>
#include <cstdint>

#define BB 2
#define SS 2048
#define DD 1024
#define HH 16
#define DK 64
#define MROWS (BB*SS)
#define NEGV -1000000000.0f

// ---------------- scratch ----------------
__device__ __align__(128) __half g_in16[(size_t)3*MROWS*DD];   // q,k,v fp16
__device__ __align__(128) __half g_a16[(size_t)MROWS*DD];      // ctx fp16
__device__ __align__(128) __half g_w16[(size_t)4*DD*DD];       // Wq,Wk,Wv,Wo fp16
__device__ __align__(128) __half g_qh16[(size_t)BB*HH*SS*DK];
__device__ __align__(128) __half g_kh16[(size_t)BB*HH*SS*DK];
__device__ __align__(128) __half g_vt16[(size_t)BB*HH*DK*SS];
__device__ __align__(128) __half g_p16[(size_t)BB*HH*SS*SS];
__device__ float g_pattn_scratch[(size_t)BB*HH*SS*SS];         // fallback

// ---------------- helpers ----------------
__device__ __forceinline__ uint32_t smem_u32(const void* p) {
    uint32_t a;
    asm("{ .reg .u64 t; cvta.to.shared.u64 t, %1; cvt.u32.u64 %0, t; }" : "=r"(a) : "l"(p));
    return a;
}

#define CP_ASYNC16(dst, src) \
    asm volatile("cp.async.cg.shared.global [%0], [%1], 16;" :: "r"(dst), "l"(src) : "memory")
#define CP_COMMIT() asm volatile("cp.async.commit_group;" ::: "memory")
#define CP_WAIT(n)  asm volatile("cp.async.wait_group %0;" :: "n"(n) : "memory")

__device__ __forceinline__ void ldm_x4(uint32_t addr, uint32_t& r0, uint32_t& r1,
                                       uint32_t& r2, uint32_t& r3) {
    asm volatile("ldmatrix.sync.aligned.m8n8.x4.shared.b16 {%0,%1,%2,%3}, [%4];"
                 : "=r"(r0), "=r"(r1), "=r"(r2), "=r"(r3) : "r"(addr));
}

__device__ __forceinline__ void mma16816(float* c, const uint32_t* a, const uint32_t* b) {
    asm volatile("mma.sync.aligned.m16n8k16.row.col.f32.f16.f16.f32 "
                 "{%0,%1,%2,%3},{%4,%5,%6,%7},{%8,%9},{%0,%1,%2,%3};"
                 : "+f"(c[0]), "+f"(c[1]), "+f"(c[2]), "+f"(c[3])
                 : "r"(a[0]), "r"(a[1]), "r"(a[2]), "r"(a[3]), "r"(b[0]), "r"(b[1]));
}

// (rows x 32 half) tile, 80B padded rows, 256 threads
__device__ __forceinline__ void ld_tile(uint32_t dst, const __half* g, int ldh,
                                        int rows, int tid) {
    for (int ci = tid; ci < rows * 4; ci += 256) {
        int r = ci >> 2, c = ci & 3;
        CP_ASYNC16(dst + (uint32_t)(r * 80 + c * 16), g + (size_t)r * ldh + c * 8);
    }
}

// ============================================================================
// fp16 MMA GEMM, 256 threads / 8 warps, 2 CTAs per SM.
// MODE: 0 proj->fp32 flat +bias | 3 scores masked fp32 | 4 AV ctx half
//       7 merged QKV proj: z=0->outH(q,(z,s,dk)), z=1->outH2(k), z=2->outH3(vT)
// ============================================================================
template<int WARPS_M, int WARPS_N, int WMI, int WNI, int S, int MODE>
__global__ __launch_bounds__(256, 2) void tc_mm(
    const __half* __restrict__ A, int lda, size_t aZ,
    const __half* __restrict__ B, int ldb, size_t bZ,
    int K,
    const float* __restrict__ bias,
    const float* __restrict__ bias2,
    const float* __restrict__ bias3,
    const int*   __restrict__ mask,
    float* __restrict__ outF,
    __half* __restrict__ outH,
    __half* __restrict__ outH2,
    __half* __restrict__ outH3)
{
    constexpr int BM  = WARPS_M * WMI * 16;
    constexpr int BN  = WARPS_N * WNI * 8;
    constexpr int BNP = BN + 5;   // odd pad for transpose staging (MODE7 z==2)
    constexpr int ASZ = BM * 80;
    constexpr int BSZ = BN * 80;
    constexpr int STG = ASZ + BSZ;
    constexpr int NJ  = WNI / 2;

    extern __shared__ char smraw[];
    char* sm = (char*)(((uintptr_t)smraw + 127) & ~(uintptr_t)127);
    uint32_t smu = smem_u32(sm);

    const int tid  = threadIdx.x;
    const int w    = tid >> 5, lane = tid & 31;
    const int bn   = blockIdx.x * BN, bm = blockIdx.y * BM;
    const int z    = blockIdx.z;

    A += (size_t)z * aZ + (size_t)bm * lda;
    B += (size_t)z * bZ + (size_t)bn * ldb;

    const int wm = (w / WARPS_N) * (WMI * 16);
    const int wn = (w % WARPS_N) * (WNI * 8);

    float acc[WMI][WNI][4];
#pragma unroll
    for (int mi = 0; mi < WMI; mi++)
#pragma unroll
        for (int nt = 0; nt < WNI; nt++)
#pragma unroll
            for (int x = 0; x < 4; x++) acc[mi][nt][x] = 0.f;

    const int NK = K / 32;
#pragma unroll
    for (int s = 0; s < S - 1; s++) {
        if (s < NK) {
            ld_tile(smu + s * STG,       A + s * 32, lda, BM, tid);
            ld_tile(smu + s * STG + ASZ, B + s * 32, ldb, BN, tid);
        }
        CP_COMMIT();
    }

    const int rA = (lane & 7) + ((lane >> 3) & 1) * 8;
    const int kO = ((lane >> 4) << 3) * 2;

    for (int kt = 0; kt < NK; kt++) {
        CP_WAIT(S - 2);
        __syncthreads();
        uint32_t sA = smu + (kt % S) * STG;
        uint32_t sB = sA + ASZ;
#pragma unroll
        for (int ks = 0; ks < 2; ks++) {
            uint32_t a[WMI][4], bf[WNI][2];
            uint32_t kb = (uint32_t)(ks * 32 + kO);
#pragma unroll
            for (int mi = 0; mi < WMI; mi++)
                ldm_x4(sA + (uint32_t)((wm + mi * 16 + rA) * 80) + kb,
                       a[mi][0], a[mi][1], a[mi][2], a[mi][3]);
#pragma unroll
            for (int nj = 0; nj < NJ; nj++) {
                uint32_t r0, r1, r2, r3;
                ldm_x4(sB + (uint32_t)((wn + nj * 16 + rA) * 80) + kb, r0, r1, r2, r3);
                bf[nj * 2 + 0][0] = r0; bf[nj * 2 + 1][0] = r1;
                bf[nj * 2 + 0][1] = r2; bf[nj * 2 + 1][1] = r3;
            }
#pragma unroll
            for (int mi = 0; mi < WMI; mi++)
#pragma unroll
                for (int nt = 0; nt < WNI; nt++)
                    mma16816(acc[mi][nt], a[mi], bf[nt]);
        }
        int ns = kt + S - 1;
        if (ns < NK) {
            ld_tile(smu + (ns % S) * STG,       A + ns * 32, lda, BM, tid);
            ld_tile(smu + (ns % S) * STG + ASZ, B + ns * 32, ldb, BN, tid);
        }
        CP_COMMIT();
    }
    CP_WAIT(0);
    __syncthreads();

    float* esm = (float*)sm;
    const int er = lane >> 2, ec = (lane & 3) * 2;

    // ---- MODE7 z==2: V projection with coalesced transpose (vT layout) ----
    if (MODE == 7 && z == 2) {
#pragma unroll
        for (int mi = 0; mi < WMI; mi++)
#pragma unroll
            for (int nt = 0; nt < WNI; nt++) {
                int r0 = wm + mi * 16 + er;
                int c0 = wn + nt * 8 + ec;
                esm[(size_t)r0 * BNP + c0]           = acc[mi][nt][0];
                esm[(size_t)r0 * BNP + c0 + 1]       = acc[mi][nt][1];
                esm[(size_t)(r0 + 8) * BNP + c0]     = acc[mi][nt][2];
                esm[(size_t)(r0 + 8) * BNP + c0 + 1] = acc[mi][nt][3];
            }
        __syncthreads();
        const int bb = bm >> 11;
        const int sbase = bm & (SS - 1);
        for (int ci = tid; ci < BN * (BM / 4); ci += 256) {
            int e  = ci >> 5;
            int mg = ci & 31;
            int eg = bn + e;
            int h = eg >> 6, dk = eg & 63;
            float bv = bias3[eg];
            float v0 = esm[(size_t)(mg * 4 + 0) * BNP + e] + bv;
            float v1 = esm[(size_t)(mg * 4 + 1) * BNP + e] + bv;
            float v2 = esm[(size_t)(mg * 4 + 2) * BNP + e] + bv;
            float v3 = esm[(size_t)(mg * 4 + 3) * BNP + e] + bv;
            __half2* dst = (__half2*)&outH3[((size_t)((bb * HH + h)) * DK + dk) * SS
                                            + sbase + mg * 4];
            dst[0] = __floats2half2_rn(v0, v1);
            dst[1] = __floats2half2_rn(v2, v3);
        }
        return;
    }

    // ---- standard staging (BN stride, vectorized) ----
#pragma unroll
    for (int mi = 0; mi < WMI; mi++)
#pragma unroll
        for (int nt = 0; nt < WNI; nt++) {
            int r0 = wm + mi * 16 + er;
            int c0 = wn + nt * 8 + ec;
            *(float2*)&esm[(size_t)r0 * BN + c0]       = make_float2(acc[mi][nt][0], acc[mi][nt][1]);
            *(float2*)&esm[(size_t)(r0 + 8) * BN + c0] = make_float2(acc[mi][nt][2], acc[mi][nt][3]);
        }
    __syncthreads();

    for (int ci = tid; ci < BM * BN / 4; ci += 256) {
        int r  = ci / (BN / 4);
        int c0 = (ci % (BN / 4)) * 4;
        float4 v = *(const float4*)&esm[(size_t)r * BN + c0];
        int m = bm + r;
        if (MODE == 0) {
            int e0 = bn + c0;
            float4 o = make_float4(v.x + bias[e0], v.y + bias[e0+1],
                                   v.z + bias[e0+2], v.w + bias[e0+3]);
            *(float4*)&outF[(size_t)m * DD + e0] = o;
        } else if (MODE == 7) {   // z==0 or z==1: head layout (z,s,dk)
            const float* bz = (z == 0) ? bias : bias2;
            __half* dsth = (z == 0) ? outH : outH2;
            int e0 = bn + c0;
            int h = e0 >> 6, dk0 = e0 & 63;
            int bb = m >> 11, s = m & (SS - 1);
            __half2 h0 = __floats2half2_rn(v.x + bz[e0],   v.y + bz[e0+1]);
            __half2 h1 = __floats2half2_rn(v.z + bz[e0+2], v.w + bz[e0+3]);
            __half2* dst = (__half2*)&dsth[(((size_t)(bb * HH + h)) * SS + s) * DK + dk0];
            dst[0] = h0; dst[1] = h1;
        } else if (MODE == 3) {
            int col0 = bn + c0;
            int bb = z >> 4;
            int4 mm = *(const int4*)&mask[((size_t)bb * SS + m) * SS + col0];
            float4 o;
            o.x = mm.x ? v.x * 0.125f : NEGV;
            o.y = mm.y ? v.y * 0.125f : NEGV;
            o.z = mm.z ? v.z * 0.125f : NEGV;
            o.w = mm.w ? v.w * 0.125f : NEGV;
            *(float4*)&outF[(size_t)z * SS * SS + (size_t)m * SS + col0] = o;
        } else { // MODE 4: ctx half (b,s,d)
            int bb = z >> 4, h = z & 15;
            __half2 h0 = __floats2half2_rn(v.x, v.y);
            __half2 h1 = __floats2half2_rn(v.z, v.w);
            __half2* dst = (__half2*)&outH[((size_t)bb * SS + m) * DD + h * DK + bn + c0];
            dst[0] = h0; dst[1] = h1;
        }
    }
}

// ======================= one merged fp32 -> fp16 convert =======================
// grid (nIn, 7): y=0..2 -> q,k,v (nIn blocks), y=3..6 -> Wq,Wk,Wv,Wo (nW blocks)
__global__ __launch_bounds__(256) void k_f2hall(
    const float* __restrict__ q, const float* __restrict__ k, const float* __restrict__ v,
    const float* __restrict__ w0, const float* __restrict__ w1,
    const float* __restrict__ w2, const float* __restrict__ w3,
    __half* __restrict__ in16, __half* __restrict__ w16, int nW)
{
    int y = blockIdx.y;
    const float* x;
    __half* dst;
    if (y < 3) {
        x = (y == 0) ? q : (y == 1) ? k : v;
        dst = in16 + (size_t)y * MROWS * DD;
    } else {
        if (blockIdx.x >= (unsigned)nW) return;
        x = (y == 3) ? w0 : (y == 4) ? w1 : (y == 5) ? w2 : w3;
        dst = w16 + (size_t)(y - 3) * DD * DD;
    }
    size_t i = ((size_t)blockIdx.x * 256 + threadIdx.x) * 4;
    float4 val = *(const float4*)(x + i);
    *(__half2*)(dst + i)     = __floats2half2_rn(val.x, val.y);
    *(__half2*)(dst + i + 2) = __floats2half2_rn(val.z, val.w);
}

// ======================= warp-per-row softmax =======================
// 8 warps/block, one row each. 64 floats per lane, shuffle-only reductions.
__global__ __launch_bounds__(256) void k_softmax_w(float* __restrict__ P,
                                                   __half* __restrict__ P16)
{
    const size_t row = (size_t)blockIdx.x * 8 + (threadIdx.x >> 5);
    const int lane = threadIdx.x & 31;
    float4* p = (float4*)(P + row * SS);
    __half2* ph = (__half2*)(P16 + row * SS);

    float4 v[16];
#pragma unroll
    for (int i = 0; i < 16; i++) v[i] = p[lane + i * 32];

    float m = -INFINITY;
#pragma unroll
    for (int i = 0; i < 16; i++)
        m = fmaxf(m, fmaxf(fmaxf(v[i].x, v[i].y), fmaxf(v[i].z, v[i].w)));
#pragma unroll
    for (int o = 16; o; o >>= 1) m = fmaxf(m, __shfl_xor_sync(~0u, m, o));

    float s = 0.f;
#pragma unroll
    for (int i = 0; i < 16; i++) {
        v[i].x = __expf(v[i].x - m);
        v[i].y = __expf(v[i].y - m);
        v[i].z = __expf(v[i].z - m);
        v[i].w = __expf(v[i].w - m);
        s += (v[i].x + v[i].y) + (v[i].z + v[i].w);
    }
#pragma unroll
    for (int o = 16; o; o >>= 1) s += __shfl_xor_sync(~0u, s, o);
    float inv = 1.0f / s;

#pragma unroll
    for (int i = 0; i < 16; i++) {
        v[i].x *= inv; v[i].y *= inv; v[i].z *= inv; v[i].w *= inv;
        p[lane + i * 32] = v[i];
        ph[(lane + i * 32) * 2 + 0] = __floats2half2_rn(v[i].x, v[i].y);
        ph[(lane + i * 32) * 2 + 1] = __floats2half2_rn(v[i].z, v[i].w);
    }
}

// ======================= launch =======================
extern "C" void kernel_launch(void* const* d_in, const int* in_sizes, int n_in,
                              void* d_out, int out_size)
{
    const float* q    = (const float*)d_in[0];
    const float* k    = (const float*)d_in[1];
    const float* v    = (const float*)d_in[2];
    const int*   mask = (const int*)  d_in[3];
    const float* Wq   = (const float*)d_in[4];
    const float* bq_  = (const float*)d_in[5];
    const float* Wk   = (const float*)d_in[6];
    const float* bk_  = (const float*)d_in[7];
    const float* Wv   = (const float*)d_in[8];
    const float* bv_  = (const float*)d_in[9];
    const float* Wo   = (const float*)d_in[10];
    const float* bo_  = (const float*)d_in[11];
    float* out = (float*)d_out;

    const long long out_elems = (long long)MROWS * DD;
    const long long p_elems   = (long long)BB * HH * SS * SS;

    float* p_base;
    if ((long long)out_size >= out_elems + p_elems) {
        p_base = out + out_elems;
    } else {
        void* sp = nullptr;
        cudaGetSymbolAddress(&sp, g_pattn_scratch);
        p_base = (float*)sp;
    }

    void *pin16, *pa16, *pw16, *pqh, *pkh, *pvt, *pp16;
    cudaGetSymbolAddress(&pin16, g_in16);
    cudaGetSymbolAddress(&pa16, g_a16);
    cudaGetSymbolAddress(&pw16, g_w16);
    cudaGetSymbolAddress(&pqh,  g_qh16);
    cudaGetSymbolAddress(&pkh,  g_kh16);
    cudaGetSymbolAddress(&pvt,  g_vt16);
    cudaGetSymbolAddress(&pp16, g_p16);
    __half* in16 = (__half*)pin16;
    __half* a16 = (__half*)pa16;
    __half* w16 = (__half*)pw16;
    __half* qh16 = (__half*)pqh;
    __half* kh16 = (__half*)pkh;
    __half* vt16 = (__half*)pvt;
    __half* p16  = (__half*)pp16;

    const size_t inOff = (size_t)MROWS * DD;
    const size_t wOff  = (size_t)DD * DD;

    const int SM_PROJ = 82048;    // 4*(128+128)*80 + align; esm 128*133*4=68KB fits
    const int SM_SC   = 65664;    // max(3*20480, esm 64KB) + align
    const int SM_AV   = 102528;   // 4*(256+64)*80 + align
    cudaFuncSetAttribute(tc_mm<2,4,4,4,4,0>, cudaFuncAttributeMaxDynamicSharedMemorySize, SM_PROJ);
    cudaFuncSetAttribute(tc_mm<2,4,4,4,4,7>, cudaFuncAttributeMaxDynamicSharedMemorySize, SM_PROJ);
    cudaFuncSetAttribute(tc_mm<2,4,4,4,3,3>, cudaFuncAttributeMaxDynamicSharedMemorySize, SM_SC);
    cudaFuncSetAttribute(tc_mm<4,2,4,4,4,4>, cudaFuncAttributeMaxDynamicSharedMemorySize, SM_AV);

    const int nIn = MROWS * DD / 1024;
    const int nW  = DD * DD / 1024;

    // all converts in one launch
    k_f2hall<<<dim3(nIn, 7), 256>>>(q, k, v, Wq, Wk, Wv, Wo, in16, w16, nW);

    // merged QKV projections: grid z = 0,1,2
    dim3 gProjQKV(DD / 128, MROWS / 128, 3);
    tc_mm<2,4,4,4,4,7><<<gProjQKV, 256, SM_PROJ>>>(in16, DD, inOff, w16, DD, wOff, DD,
        bq_, bk_, bv_, nullptr, nullptr, qh16, kh16, vt16);

    // scores (raw masked scaled) -> fp32 P
    dim3 gScores(SS / 128, SS / 128, BB * HH);
    tc_mm<2,4,4,4,3,3><<<gScores, 256, SM_SC>>>(qh16, DK, (size_t)SS * DK,
        kh16, DK, (size_t)SS * DK, DK,
        nullptr, nullptr, nullptr, mask, p_base, nullptr, nullptr, nullptr);

    // warp-per-row softmax + fp16 copy
    k_softmax_w<<<BB * HH * SS / 8, 256>>>(p_base, p16);

    // AV: ctx = P16 @ Vt^T   (BM=256, BN=64, warp tile 64x32)
    dim3 gAV(1, SS / 256, BB * HH);
    tc_mm<4,2,4,4,4,4><<<gAV, 256, SM_AV>>>(p16, SS, (size_t)SS * SS,
        vt16, SS, (size_t)DK * SS, SS,
        nullptr, nullptr, nullptr, nullptr, nullptr, a16, nullptr, nullptr);

    // output projection
    dim3 gProj(DD / 128, MROWS / 128, 1);
    tc_mm<2,4,4,4,4,0><<<gProj, 256, SM_PROJ>>>(a16, DD, 0, w16 + 3 * wOff, DD, 0, DD,
        bo_, nullptr, nullptr, nullptr, out, nullptr, nullptr, nullptr);
}